// round 5
// baseline (speedup 1.0000x reference)
#include <cuda_runtime.h>

#define HW    16384
#define BATCH 8
#define CDIM  192
#define HEADS 6
#define CH    32
#define NROWS (BATCH*CDIM)      /* 1536 */
#define NBH   (BATCH*HEADS)     /* 48   */
#define ATT_CHUNKS 8
#define ATT_CHUNK  (HW/ATT_CHUNKS)

/* ------------------------------------------------------------------ */
/* Scratch (device globals: no allocations allowed)                    */
/* ------------------------------------------------------------------ */
__device__ float g_qp[BATCH*CDIM*HW];
__device__ float g_kp[BATCH*CDIM*HW];
__device__ float g_vp[BATCH*CDIM*HW];
__device__ float g_attn[NBH*CH*CH];      /* raw logits -> probs */
__device__ float g_ss[2*NROWS];          /* [0:1536) q sumsq, [1536:) k sumsq */
__device__ float g_weff[BATCH*CDIM*CDIM];

/* ------------------------------------------------------------------ */
/* Zero the accumulators (graph replays require re-zeroing each run)   */
/* ------------------------------------------------------------------ */
__global__ void zero_kernel() {
    int i = blockIdx.x * 256 + threadIdx.x;
    if (i < NBH*CH*CH) g_attn[i] = 0.f;
    if (i < 2*NROWS)   g_ss[i]   = 0.f;
}

/* ------------------------------------------------------------------ */
/* conv1x1 as SGEMM:  Y[b][m][n] = sum_k W[m][k] * X[b][k][n] + bias[m]
 * 64x64 tile, BK=16, 256 threads, 4x4 per-thread microtile.
 * wstride = 0 (shared weights) or CDIM*CDIM (per-batch Weff).        */
/* ------------------------------------------------------------------ */
__global__ void __launch_bounds__(256)
conv_gemm(const float* __restrict__ X, const float* __restrict__ W,
          const float* __restrict__ bias, float* __restrict__ Y, int wstride)
{
    __shared__ float As[16][64];   /* As[k][m] */
    __shared__ float Bs[16][64];   /* Bs[k][n] */

    const int n0 = blockIdx.x * 64;
    const int bm = blockIdx.y;
    const int bb = bm / 3;
    const int m0 = (bm % 3) * 64;

    const float* Wb = W + (size_t)bb * wstride;
    const float* Xb = X + (size_t)bb * CDIM * HW;
    float*       Yb = Y + (size_t)bb * CDIM * HW;

    const int tid = threadIdx.x;
    const int tn  = tid & 15;         /* 0..15 : n microtile */
    const int tm  = tid >> 4;         /* 0..15 : m microtile */
    const int lm  = tid & 63;         /* As load: m index     */
    const int lk  = tid >> 6;         /* As load: base k      */
    const int bk  = tid >> 4;         /* Bs load: k index     */
    const int bn  = (tid & 15) << 2;  /* Bs load: n index     */

    float acc[4][4];
    #pragma unroll
    for (int i = 0; i < 4; i++)
        #pragma unroll
        for (int j = 0; j < 4; j++) acc[i][j] = 0.f;

    for (int k0 = 0; k0 < CDIM; k0 += 16) {
        #pragma unroll
        for (int j = 0; j < 4; j++)
            As[lk + 4*j][lm] = Wb[(m0 + lm) * CDIM + k0 + lk + 4*j];
        *(float4*)&Bs[bk][bn] =
            *(const float4*)&Xb[(size_t)(k0 + bk) * HW + n0 + bn];
        __syncthreads();

        #pragma unroll
        for (int k = 0; k < 16; k++) {
            float4 av = *(const float4*)&As[k][tm << 2];
            float4 bv = *(const float4*)&Bs[k][tn << 2];
            float a4[4] = {av.x, av.y, av.z, av.w};
            float b4[4] = {bv.x, bv.y, bv.z, bv.w};
            #pragma unroll
            for (int i = 0; i < 4; i++)
                #pragma unroll
                for (int j = 0; j < 4; j++)
                    acc[i][j] += a4[i] * b4[j];
        }
        __syncthreads();
    }

    #pragma unroll
    for (int i = 0; i < 4; i++) {
        int m = m0 + (tm << 2) + i;
        float bz = bias[m];
        float4 r = make_float4(acc[i][0]+bz, acc[i][1]+bz, acc[i][2]+bz, acc[i][3]+bz);
        *(float4*)&Yb[(size_t)m * HW + n0 + (tn << 2)] = r;
    }
}

/* ------------------------------------------------------------------ */
/* Fused raw logits (QP . KP^T over n) + row sum-of-squares.
 * One block per (bh, chunk). 8 warps, each warp owns 4 q-rows and
 * accumulates against all 32 k-rows (k-rows L1-resident across warps).*/
/* ------------------------------------------------------------------ */
__global__ void __launch_bounds__(256)
attn_kernel(const float* __restrict__ qp, const float* __restrict__ kp)
{
    const int bh   = blockIdx.x;            /* 0..47 */
    const int ch   = blockIdx.y;            /* 0..7  */
    const int warp = threadIdx.x >> 5;      /* 0..7  */
    const int lane = threadIdx.x & 31;
    const int b  = bh / HEADS;
    const int hh = bh % HEADS;

    const float* Q = qp + (size_t)(b*CDIM + hh*CH) * HW;
    const float* K = kp + (size_t)(b*CDIM + hh*CH) * HW;
    const int c0 = warp * 4;
    const int n0 = ch * ATT_CHUNK;

    float acc[4][32];
    #pragma unroll
    for (int i = 0; i < 4; i++)
        #pragma unroll
        for (int d = 0; d < 32; d++) acc[i][d] = 0.f;
    float qs[4] = {0.f,0.f,0.f,0.f};
    float ks[4] = {0.f,0.f,0.f,0.f};

    for (int n = n0 + lane; n < n0 + ATT_CHUNK; n += 32) {
        float qv[4];
        #pragma unroll
        for (int i = 0; i < 4; i++) {
            qv[i] = Q[(size_t)(c0 + i) * HW + n];
            qs[i] += qv[i] * qv[i];
        }
        #pragma unroll
        for (int i = 0; i < 4; i++) {
            float kc = K[(size_t)(c0 + i) * HW + n];   /* L1 hit (re-read below) */
            ks[i] += kc * kc;
        }
        #pragma unroll
        for (int d = 0; d < 32; d++) {
            float kv = K[(size_t)d * HW + n];
            #pragma unroll
            for (int i = 0; i < 4; i++) acc[i][d] += qv[i] * kv;
        }
    }

    /* reduce dot products across lanes; lane d keeps S[c][d] */
    #pragma unroll
    for (int i = 0; i < 4; i++) {
        float out = 0.f;
        #pragma unroll
        for (int d = 0; d < 32; d++) {
            float v = acc[i][d];
            v += __shfl_xor_sync(0xffffffffu, v, 16);
            v += __shfl_xor_sync(0xffffffffu, v, 8);
            v += __shfl_xor_sync(0xffffffffu, v, 4);
            v += __shfl_xor_sync(0xffffffffu, v, 2);
            v += __shfl_xor_sync(0xffffffffu, v, 1);
            if (lane == d) out = v;
        }
        atomicAdd(&g_attn[bh*CH*CH + (c0 + i)*CH + lane], out);
    }

    /* reduce sumsq */
    #pragma unroll
    for (int i = 0; i < 4; i++) {
        float vq = qs[i], vk = ks[i];
        vq += __shfl_xor_sync(0xffffffffu, vq, 16);
        vq += __shfl_xor_sync(0xffffffffu, vq, 8);
        vq += __shfl_xor_sync(0xffffffffu, vq, 4);
        vq += __shfl_xor_sync(0xffffffffu, vq, 2);
        vq += __shfl_xor_sync(0xffffffffu, vq, 1);
        vk += __shfl_xor_sync(0xffffffffu, vk, 16);
        vk += __shfl_xor_sync(0xffffffffu, vk, 8);
        vk += __shfl_xor_sync(0xffffffffu, vk, 4);
        vk += __shfl_xor_sync(0xffffffffu, vk, 2);
        vk += __shfl_xor_sync(0xffffffffu, vk, 1);
        if (lane == 0) {
            int row = b*CDIM + hh*CH + c0 + i;
            atomicAdd(&g_ss[row], vq);
            atomicAdd(&g_ss[NROWS + row], vk);
        }
    }
}

/* ------------------------------------------------------------------ */
/* Softmax over d with L2-norm scaling + temperature folded in.        */
/* grid=48, block=(32,32): y = c (one warp per row), x = d (lane).     */
/* ------------------------------------------------------------------ */
__global__ void softmax_kernel(const float* __restrict__ temp)
{
    const int bh = blockIdx.x;
    const int b  = bh / HEADS;
    const int hh = bh % HEADS;
    const int c  = threadIdx.y;
    const int d  = threadIdx.x;

    const int rowq = b*CDIM + hh*CH + c;
    const int rowk = b*CDIM + hh*CH + d;
    float rq = 1.f / fmaxf(sqrtf(g_ss[rowq]), 1e-12f);
    float rk = 1.f / fmaxf(sqrtf(g_ss[NROWS + rowk]), 1e-12f);

    int idx = bh*CH*CH + c*CH + d;
    float v = g_attn[idx] * rq * rk * temp[hh];

    float m = v;
    m = fmaxf(m, __shfl_xor_sync(0xffffffffu, m, 16));
    m = fmaxf(m, __shfl_xor_sync(0xffffffffu, m, 8));
    m = fmaxf(m, __shfl_xor_sync(0xffffffffu, m, 4));
    m = fmaxf(m, __shfl_xor_sync(0xffffffffu, m, 2));
    m = fmaxf(m, __shfl_xor_sync(0xffffffffu, m, 1));
    float e = __expf(v - m);
    float s = e;
    s += __shfl_xor_sync(0xffffffffu, s, 16);
    s += __shfl_xor_sync(0xffffffffu, s, 8);
    s += __shfl_xor_sync(0xffffffffu, s, 4);
    s += __shfl_xor_sync(0xffffffffu, s, 2);
    s += __shfl_xor_sync(0xffffffffu, s, 1);
    g_attn[idx] = e / s;
}

/* ------------------------------------------------------------------ */
/* Fold attention probs into output projection:
 * Weff[b][o][h*32+dc] = sum_c Wo[o][h*32+c] * P[b,h][c][dc]          */
/* ------------------------------------------------------------------ */
__global__ void weff_kernel(const float* __restrict__ wo)
{
    const int b   = blockIdx.y;
    const int idx = blockIdx.x * 256 + threadIdx.x;   /* < 192*192 */
    const int o   = idx / CDIM;
    const int dg  = idx % CDIM;
    const int h   = dg / CH;
    const int dc  = dg % CH;

    const float* P    = g_attn + ((b*HEADS + h)*CH)*CH;
    const float* wrow = wo + o*CDIM + h*CH;
    float s = 0.f;
    #pragma unroll
    for (int c = 0; c < CH; c++)
        s += wrow[c] * P[c*CH + dc];
    g_weff[((size_t)b*CDIM + o)*CDIM + dg] = s;
}

/* ------------------------------------------------------------------ */
extern "C" void kernel_launch(void* const* d_in, const int* in_sizes, int n_in,
                              void* d_out, int out_size)
{
    const float* q    = (const float*)d_in[0];
    const float* k    = (const float*)d_in[1];
    const float* v    = (const float*)d_in[2];
    const float* wq   = (const float*)d_in[3];
    const float* bq   = (const float*)d_in[4];
    const float* wk   = (const float*)d_in[5];
    const float* bk   = (const float*)d_in[6];
    const float* wv   = (const float*)d_in[7];
    const float* bv   = (const float*)d_in[8];
    const float* wo   = (const float*)d_in[9];
    const float* bo   = (const float*)d_in[10];
    const float* temp = (const float*)d_in[11];

    float *qp, *kp, *vp, *weff;
    cudaGetSymbolAddress((void**)&qp,   g_qp);
    cudaGetSymbolAddress((void**)&kp,   g_kp);
    cudaGetSymbolAddress((void**)&vp,   g_vp);
    cudaGetSymbolAddress((void**)&weff, g_weff);

    zero_kernel<<<(NBH*CH*CH + 255)/256, 256>>>();

    dim3 gg(HW/64, BATCH*3);
    conv_gemm<<<gg, 256>>>(q, wq, bq, qp, 0);
    conv_gemm<<<gg, 256>>>(k, wk, bk, kp, 0);
    conv_gemm<<<gg, 256>>>(v, wv, bv, vp, 0);

    attn_kernel<<<dim3(NBH, ATT_CHUNKS), 256>>>(qp, kp);
    softmax_kernel<<<NBH, dim3(32, 32)>>>(temp);
    weff_kernel<<<dim3((CDIM*CDIM)/256, BATCH), 256>>>(wo);

    conv_gemm<<<gg, 256>>>(vp, weff, bo, (float*)d_out, CDIM*CDIM);
}

// round 7
// speedup vs baseline: 1.9216x; 1.9216x over previous
#include <cuda_runtime.h>
#include <cuda_bf16.h>
#include <cstdint>

#define HW    16384
#define BATCH 8
#define CDIM  192
#define HEADS 6
#define CH    32
#define NROWS (BATCH*CDIM)      /* 1536 */
#define NBH   (BATCH*HEADS)     /* 48   */
#define ATT_CHUNKS 8
#define ATT_CHUNK  (HW/ATT_CHUNKS)
#define WSZ   (CDIM*CDIM)       /* 36864 */

/* ------------------------------------------------------------------ */
/* Scratch (device globals: no allocations allowed)                    */
/* ------------------------------------------------------------------ */
__device__ float g_qp[BATCH*CDIM*HW];
__device__ float g_kp[BATCH*CDIM*HW];
__device__ float g_vp[BATCH*CDIM*HW];
__device__ float g_attn[NBH*CH*CH];
__device__ float g_ss[2*NROWS];
__device__ __nv_bfloat16 g_wh[3*WSZ];        /* wq,wk,wv hi */
__device__ __nv_bfloat16 g_wl[3*WSZ];        /* wq,wk,wv lo */
__device__ __nv_bfloat16 g_weffh[BATCH*WSZ];
__device__ __nv_bfloat16 g_weffl[BATCH*WSZ];

/* ------------------------------------------------------------------ */
__global__ void zero_kernel() {
    int i = blockIdx.x * 256 + threadIdx.x;
    if (i < NBH*CH*CH) g_attn[i] = 0.f;
    if (i < 2*NROWS)   g_ss[i]   = 0.f;
}

/* Split wq/wk/wv into bf16 hi/lo */
__global__ void prep_w(const float* __restrict__ wq,
                       const float* __restrict__ wk,
                       const float* __restrict__ wv)
{
    int i = blockIdx.x * 256 + threadIdx.x;
    if (i >= 3*WSZ) return;
    const float* src = (i < WSZ) ? wq : (i < 2*WSZ ? wk : wv);
    float x = src[i % WSZ];
    __nv_bfloat16 h = __float2bfloat16(x);
    g_wh[i] = h;
    g_wl[i] = __float2bfloat16(x - __bfloat162float(h));
}

/* ------------------------------------------------------------------ */
/* bf16-split tensor-core conv1x1 via mma.sync.m16n8k16:
 * Y[b][m][n] = sum_k W[m][k] X[b][k][n] + bias[m]
 * CTA: 64(M) x 128(N); 8 warps as 2(M) x 4(N), warp tile 32x32.
 * K=192 in 3 chunks of 64. A frags via LDG (L1-resident weights),
 * B in SMEM transposed to [n][k-pair u32], stride 37 words.          */
/* ------------------------------------------------------------------ */
#define BSTR 37   /* words per n-row: 32 k-pairs + 5 pad (conflict-free frag loads) */

__device__ __forceinline__ void mma_bf16(float* c, const uint32_t* a, const uint32_t* b) {
    asm volatile(
        "mma.sync.aligned.m16n8k16.row.col.f32.bf16.bf16.f32 "
        "{%0,%1,%2,%3}, {%4,%5,%6,%7}, {%8,%9}, {%0,%1,%2,%3};"
        : "+f"(c[0]), "+f"(c[1]), "+f"(c[2]), "+f"(c[3])
        : "r"(a[0]), "r"(a[1]), "r"(a[2]), "r"(a[3]), "r"(b[0]), "r"(b[1]));
}

__global__ void __launch_bounds__(256)
gemm_bf16(const float* __restrict__ X,
          const __nv_bfloat16* __restrict__ Whi,
          const __nv_bfloat16* __restrict__ Wlo,
          const float* __restrict__ bias,
          float* __restrict__ Y, int wstride)
{
    __shared__ uint32_t Bs_hi[128*BSTR];
    __shared__ uint32_t Bs_lo[128*BSTR];

    const int tid  = threadIdx.x;
    const int wid  = tid >> 5;
    const int lane = tid & 31;
    const int grp  = lane >> 2;      /* 0..7 */
    const int tig  = lane & 3;       /* 0..3 */
    const int wm   = wid & 1;        /* M half     */
    const int wn   = wid >> 1;       /* N quarter  */

    const int n0 = blockIdx.x * 128;
    const int m0 = blockIdx.y * 64;
    const int b  = blockIdx.z;

    const float* Xb = X + (size_t)b * CDIM * HW;
    float*       Yb = Y + (size_t)b * CDIM * HW;
    const __nv_bfloat16* Wh = Whi + (size_t)b * wstride;
    const __nv_bfloat16* Wl = Wlo + (size_t)b * wstride;

    float acc[2][4][4];
    #pragma unroll
    for (int i = 0; i < 2; i++)
        #pragma unroll
        for (int j = 0; j < 4; j++)
            #pragma unroll
            for (int r = 0; r < 4; r++) acc[i][j][r] = 0.f;

    for (int c = 0; c < 3; c++) {
        const int k0 = c * 64;

        /* load + split + transpose X chunk: [64 k][128 n] -> Bs[n][kpair] */
        #pragma unroll
        for (int u = tid; u < 1024; u += 256) {
            int kp = u >> 5;                 /* k-pair 0..31 */
            int nq = (u & 31) << 2;          /* n quad       */
            const float* p0 = Xb + (size_t)(k0 + 2*kp) * HW + n0 + nq;
            float4 xa = *(const float4*)p0;
            float4 xb = *(const float4*)(p0 + HW);
            float av[4] = {xa.x, xa.y, xa.z, xa.w};
            float bv[4] = {xb.x, xb.y, xb.z, xb.w};
            #pragma unroll
            for (int j = 0; j < 4; j++) {
                __nv_bfloat16 ah = __float2bfloat16(av[j]);
                __nv_bfloat16 bh = __float2bfloat16(bv[j]);
                __nv_bfloat16 al = __float2bfloat16(av[j] - __bfloat162float(ah));
                __nv_bfloat16 bl = __float2bfloat16(bv[j] - __bfloat162float(bh));
                int n = nq + j;
                Bs_hi[n*BSTR + kp] = (uint32_t)__bfloat16_as_ushort(ah)
                                   | ((uint32_t)__bfloat16_as_ushort(bh) << 16);
                Bs_lo[n*BSTR + kp] = (uint32_t)__bfloat16_as_ushort(al)
                                   | ((uint32_t)__bfloat16_as_ushort(bl) << 16);
            }
        }
        __syncthreads();

        #pragma unroll
        for (int s = 0; s < 4; s++) {
            const int kg = k0 + s * 16;
            /* A fragments via LDG (L1 hits) */
            uint32_t ah[2][4], al[2][4];
            #pragma unroll
            for (int mf = 0; mf < 2; mf++) {
                int mr = m0 + wm*32 + mf*16 + grp;
                int ka = kg + tig*2;
                const __nv_bfloat16* ph = Wh + mr*CDIM + ka;
                const __nv_bfloat16* pl = Wl + mr*CDIM + ka;
                ah[mf][0] = *(const uint32_t*)(ph);
                ah[mf][1] = *(const uint32_t*)(ph + 8*CDIM);
                ah[mf][2] = *(const uint32_t*)(ph + 8);
                ah[mf][3] = *(const uint32_t*)(ph + 8*CDIM + 8);
                al[mf][0] = *(const uint32_t*)(pl);
                al[mf][1] = *(const uint32_t*)(pl + 8*CDIM);
                al[mf][2] = *(const uint32_t*)(pl + 8);
                al[mf][3] = *(const uint32_t*)(pl + 8*CDIM + 8);
            }
            /* B fragments from SMEM (conflict-free) */
            uint32_t bh[4][2], bl[4][2];
            #pragma unroll
            for (int nf = 0; nf < 4; nf++) {
                int nn = wn*32 + nf*8 + grp;
                int w0 = nn*BSTR + s*8 + tig;
                bh[nf][0] = Bs_hi[w0];
                bh[nf][1] = Bs_hi[w0 + 4];
                bl[nf][0] = Bs_lo[w0];
                bl[nf][1] = Bs_lo[w0 + 4];
            }
            /* hh + hl + lh into the same fp32 accumulators */
            #pragma unroll
            for (int mf = 0; mf < 2; mf++)
                #pragma unroll
                for (int nf = 0; nf < 4; nf++) {
                    mma_bf16(acc[mf][nf], ah[mf], bh[nf]);
                    mma_bf16(acc[mf][nf], ah[mf], bl[nf]);
                    mma_bf16(acc[mf][nf], al[mf], bh[nf]);
                }
        }
        __syncthreads();
    }

    /* epilogue: c0,c1 -> (row, col..col+1); c2,c3 -> row+8 */
    #pragma unroll
    for (int mf = 0; mf < 2; mf++) {
        int mr = m0 + wm*32 + mf*16 + grp;
        float bz0 = __ldg(&bias[mr]);
        float bz1 = __ldg(&bias[mr + 8]);
        #pragma unroll
        for (int nf = 0; nf < 4; nf++) {
            int n = n0 + wn*32 + nf*8 + tig*2;
            *(float2*)&Yb[(size_t)mr * HW + n] =
                make_float2(acc[mf][nf][0] + bz0, acc[mf][nf][1] + bz0);
            *(float2*)&Yb[(size_t)(mr + 8) * HW + n] =
                make_float2(acc[mf][nf][2] + bz1, acc[mf][nf][3] + bz1);
        }
    }
}

/* ------------------------------------------------------------------ */
/* Fused raw logits (QP . KP^T over n) + row sum-of-squares.           */
/* ------------------------------------------------------------------ */
__global__ void __launch_bounds__(256)
attn_kernel(const float* __restrict__ qp, const float* __restrict__ kp)
{
    const int bh   = blockIdx.x;
    const int ch   = blockIdx.y;
    const int warp = threadIdx.x >> 5;
    const int lane = threadIdx.x & 31;
    const int b  = bh / HEADS;
    const int hh = bh % HEADS;

    const float* Q = qp + (size_t)(b*CDIM + hh*CH) * HW;
    const float* K = kp + (size_t)(b*CDIM + hh*CH) * HW;
    const int c0 = warp * 4;
    const int n0 = ch * ATT_CHUNK;

    float acc[4][32];
    #pragma unroll
    for (int i = 0; i < 4; i++)
        #pragma unroll
        for (int d = 0; d < 32; d++) acc[i][d] = 0.f;
    float qs[4] = {0.f,0.f,0.f,0.f};
    float ks[4] = {0.f,0.f,0.f,0.f};

    for (int n = n0 + lane; n < n0 + ATT_CHUNK; n += 32) {
        float qv[4];
        #pragma unroll
        for (int i = 0; i < 4; i++) {
            qv[i] = Q[(size_t)(c0 + i) * HW + n];
            qs[i] += qv[i] * qv[i];
        }
        #pragma unroll
        for (int i = 0; i < 4; i++) {
            float kc = K[(size_t)(c0 + i) * HW + n];
            ks[i] += kc * kc;
        }
        #pragma unroll
        for (int d = 0; d < 32; d++) {
            float kv = K[(size_t)d * HW + n];
            #pragma unroll
            for (int i = 0; i < 4; i++) acc[i][d] += qv[i] * kv;
        }
    }

    #pragma unroll
    for (int i = 0; i < 4; i++) {
        float out = 0.f;
        #pragma unroll
        for (int d = 0; d < 32; d++) {
            float v = acc[i][d];
            v += __shfl_xor_sync(0xffffffffu, v, 16);
            v += __shfl_xor_sync(0xffffffffu, v, 8);
            v += __shfl_xor_sync(0xffffffffu, v, 4);
            v += __shfl_xor_sync(0xffffffffu, v, 2);
            v += __shfl_xor_sync(0xffffffffu, v, 1);
            if (lane == d) out = v;
        }
        atomicAdd(&g_attn[bh*CH*CH + (c0 + i)*CH + lane], out);
    }

    #pragma unroll
    for (int i = 0; i < 4; i++) {
        float vq = qs[i], vk = ks[i];
        vq += __shfl_xor_sync(0xffffffffu, vq, 16);
        vq += __shfl_xor_sync(0xffffffffu, vq, 8);
        vq += __shfl_xor_sync(0xffffffffu, vq, 4);
        vq += __shfl_xor_sync(0xffffffffu, vq, 2);
        vq += __shfl_xor_sync(0xffffffffu, vq, 1);
        vk += __shfl_xor_sync(0xffffffffu, vk, 16);
        vk += __shfl_xor_sync(0xffffffffu, vk, 8);
        vk += __shfl_xor_sync(0xffffffffu, vk, 4);
        vk += __shfl_xor_sync(0xffffffffu, vk, 2);
        vk += __shfl_xor_sync(0xffffffffu, vk, 1);
        if (lane == 0) {
            int row = b*CDIM + hh*CH + c0 + i;
            atomicAdd(&g_ss[row], vq);
            atomicAdd(&g_ss[NROWS + row], vk);
        }
    }
}

/* ------------------------------------------------------------------ */
__global__ void softmax_kernel(const float* __restrict__ temp)
{
    const int bh = blockIdx.x;
    const int b  = bh / HEADS;
    const int hh = bh % HEADS;
    const int c  = threadIdx.y;
    const int d  = threadIdx.x;

    const int rowq = b*CDIM + hh*CH + c;
    const int rowk = b*CDIM + hh*CH + d;
    float rq = 1.f / fmaxf(sqrtf(g_ss[rowq]), 1e-12f);
    float rk = 1.f / fmaxf(sqrtf(g_ss[NROWS + rowk]), 1e-12f);

    int idx = bh*CH*CH + c*CH + d;
    float v = g_attn[idx] * rq * rk * temp[hh];

    float m = v;
    m = fmaxf(m, __shfl_xor_sync(0xffffffffu, m, 16));
    m = fmaxf(m, __shfl_xor_sync(0xffffffffu, m, 8));
    m = fmaxf(m, __shfl_xor_sync(0xffffffffu, m, 4));
    m = fmaxf(m, __shfl_xor_sync(0xffffffffu, m, 2));
    m = fmaxf(m, __shfl_xor_sync(0xffffffffu, m, 1));
    float e = __expf(v - m);
    float s = e;
    s += __shfl_xor_sync(0xffffffffu, s, 16);
    s += __shfl_xor_sync(0xffffffffu, s, 8);
    s += __shfl_xor_sync(0xffffffffu, s, 4);
    s += __shfl_xor_sync(0xffffffffu, s, 2);
    s += __shfl_xor_sync(0xffffffffu, s, 1);
    g_attn[idx] = e / s;
}

/* ------------------------------------------------------------------ */
/* Fold attention probs into Wo; emit bf16 hi/lo directly.             */
/* ------------------------------------------------------------------ */
__global__ void weff_kernel(const float* __restrict__ wo)
{
    const int b   = blockIdx.y;
    const int idx = blockIdx.x * 256 + threadIdx.x;
    const int o   = idx / CDIM;
    const int dg  = idx % CDIM;
    const int h   = dg / CH;
    const int dc  = dg % CH;

    const float* P    = g_attn + ((b*HEADS + h)*CH)*CH;
    const float* wrow = wo + o*CDIM + h*CH;
    float s = 0.f;
    #pragma unroll
    for (int c = 0; c < CH; c++)
        s += wrow[c] * P[c*CH + dc];

    size_t off = (size_t)b*WSZ + o*CDIM + dg;
    __nv_bfloat16 hw = __float2bfloat16(s);
    g_weffh[off] = hw;
    g_weffl[off] = __float2bfloat16(s - __bfloat162float(hw));
}

/* ------------------------------------------------------------------ */
extern "C" void kernel_launch(void* const* d_in, const int* in_sizes, int n_in,
                              void* d_out, int out_size)
{
    const float* q    = (const float*)d_in[0];
    const float* k    = (const float*)d_in[1];
    const float* v    = (const float*)d_in[2];
    const float* wq   = (const float*)d_in[3];
    const float* bq   = (const float*)d_in[4];
    const float* wk   = (const float*)d_in[5];
    const float* bk   = (const float*)d_in[6];
    const float* wv   = (const float*)d_in[7];
    const float* bv   = (const float*)d_in[8];
    const float* wo   = (const float*)d_in[9];
    const float* bo   = (const float*)d_in[10];
    const float* temp = (const float*)d_in[11];

    float *qp, *kp, *vp;
    __nv_bfloat16 *wh, *wl, *weh, *wel;
    cudaGetSymbolAddress((void**)&qp,  g_qp);
    cudaGetSymbolAddress((void**)&kp,  g_kp);
    cudaGetSymbolAddress((void**)&vp,  g_vp);
    cudaGetSymbolAddress((void**)&wh,  g_wh);
    cudaGetSymbolAddress((void**)&wl,  g_wl);
    cudaGetSymbolAddress((void**)&weh, g_weffh);
    cudaGetSymbolAddress((void**)&wel, g_weffl);

    zero_kernel<<<(NBH*CH*CH + 255)/256, 256>>>();
    prep_w<<<(3*WSZ + 255)/256, 256>>>(wq, wk, wv);

    dim3 gg(HW/128, CDIM/64, BATCH);
    gemm_bf16<<<gg, 256>>>(q, wh + 0*WSZ, wl + 0*WSZ, bq, qp, 0);
    gemm_bf16<<<gg, 256>>>(k, wh + 1*WSZ, wl + 1*WSZ, bk, kp, 0);
    gemm_bf16<<<gg, 256>>>(v, wh + 2*WSZ, wl + 2*WSZ, bv, vp, 0);

    attn_kernel<<<dim3(NBH, ATT_CHUNKS), 256>>>(qp, kp);
    softmax_kernel<<<NBH, dim3(32, 32)>>>(temp);
    weff_kernel<<<dim3((CDIM*CDIM)/256, BATCH), 256>>>(wo);

    gemm_bf16<<<gg, 256>>>(vp, weh, wel, bo, (float*)d_out, WSZ);
}

// round 8
// speedup vs baseline: 3.1781x; 1.6539x over previous
#include <cuda_runtime.h>
#include <cuda_bf16.h>
#include <cstdint>

#define HW    16384
#define BATCH 8
#define CDIM  192
#define HEADS 6
#define CH    32
#define NROWS (BATCH*CDIM)      /* 1536 */
#define NBH   (BATCH*HEADS)     /* 48   */
#define ATT_CHUNKS 8
#define ATT_CHUNK  (HW/ATT_CHUNKS)
#define WSZ   (CDIM*CDIM)       /* 36864 */

/* ------------------------------------------------------------------ */
/* Scratch (device globals: no allocations allowed)                    */
/* ------------------------------------------------------------------ */
__device__ float g_qp[BATCH*CDIM*HW];
__device__ float g_kp[BATCH*CDIM*HW];
__device__ float g_vp[BATCH*CDIM*HW];
__device__ float g_attn[NBH*CH*CH];
__device__ float g_ss[2*NROWS];
__device__ __nv_bfloat16 g_wh[3*WSZ];        /* wq,wk,wv hi */
__device__ __nv_bfloat16 g_wl[3*WSZ];        /* wq,wk,wv lo */
__device__ __nv_bfloat16 g_weffh[BATCH*WSZ];
__device__ __nv_bfloat16 g_weffl[BATCH*WSZ];

/* ------------------------------------------------------------------ */
__global__ void zero_kernel() {
    int i = blockIdx.x * 256 + threadIdx.x;
    if (i < NBH*CH*CH) g_attn[i] = 0.f;
    if (i < 2*NROWS)   g_ss[i]   = 0.f;
}

/* Split wq/wk/wv into bf16 hi/lo */
__global__ void prep_w(const float* __restrict__ wq,
                       const float* __restrict__ wk,
                       const float* __restrict__ wv)
{
    int i = blockIdx.x * 256 + threadIdx.x;
    if (i >= 3*WSZ) return;
    const float* src = (i < WSZ) ? wq : (i < 2*WSZ ? wk : wv);
    float x = src[i % WSZ];
    __nv_bfloat16 h = __float2bfloat16(x);
    g_wh[i] = h;
    g_wl[i] = __float2bfloat16(x - __bfloat162float(h));
}

/* ------------------------------------------------------------------ */
/* bf16-split tensor-core conv1x1, ldmatrix-fed mma.sync.m16n8k16.
 * CTA: 64(M=cout) x 128(N=spatial); 8 warps = 2(M) x 4(N), 32x32 warp
 * tile. K=192 in 3 chunks of 64. Both operands staged in SMEM with
 * 72-half row stride (144B: 16B-aligned, conflict-free ldmatrix).     */
/* ------------------------------------------------------------------ */
#define ASTR 36                       /* u32 words per SMEM row */
#define SA_HI 0
#define SA_LO (64*ASTR)               /* words */
#define SB_HI (2*64*ASTR)
#define SB_LO (2*64*ASTR + 128*ASTR)
#define S_WORDS (2*64*ASTR + 2*128*ASTR)   /* 13824 words = 55296 B */

__device__ __forceinline__ uint32_t smem_u32(const void* p) {
    uint32_t a;
    asm("{ .reg .u64 t; cvta.to.shared.u64 t, %1; cvt.u32.u64 %0, t; }"
        : "=r"(a) : "l"(p));
    return a;
}
__device__ __forceinline__ void ldm_x4(uint32_t* r, uint32_t addr) {
    asm volatile("ldmatrix.sync.aligned.m8n8.x4.shared.b16 {%0,%1,%2,%3}, [%4];"
        : "=r"(r[0]), "=r"(r[1]), "=r"(r[2]), "=r"(r[3]) : "r"(addr));
}
__device__ __forceinline__ void mma_bf16(float* c, const uint32_t* a, const uint32_t* b) {
    asm volatile(
        "mma.sync.aligned.m16n8k16.row.col.f32.bf16.bf16.f32 "
        "{%0,%1,%2,%3}, {%4,%5,%6,%7}, {%8,%9}, {%0,%1,%2,%3};"
        : "+f"(c[0]), "+f"(c[1]), "+f"(c[2]), "+f"(c[3])
        : "r"(a[0]), "r"(a[1]), "r"(a[2]), "r"(a[3]), "r"(b[0]), "r"(b[1]));
}

__global__ void __launch_bounds__(256, 2)
gemm_bf16(const float* __restrict__ X,
          const __nv_bfloat16* __restrict__ Whi,
          const __nv_bfloat16* __restrict__ Wlo,
          const float* __restrict__ bias,
          float* __restrict__ Y, int wstride)
{
    extern __shared__ uint32_t sm[];
    const uint32_t sbase = smem_u32(sm);

    const int tid  = threadIdx.x;
    const int wid  = tid >> 5;
    const int lane = tid & 31;
    const int grp  = lane >> 2;      /* 0..7 */
    const int tig  = lane & 3;       /* 0..3 */
    const int wm   = wid & 1;
    const int wn   = wid >> 1;

    const int n0 = blockIdx.x * 128;
    const int m0 = blockIdx.y * 64;
    const int b  = blockIdx.z;

    const float* Xb = X + (size_t)b * CDIM * HW;
    float*       Yb = Y + (size_t)b * CDIM * HW;
    const __nv_bfloat16* Wh = Whi + (size_t)b * wstride;
    const __nv_bfloat16* Wl = Wlo + (size_t)b * wstride;

    float acc[2][4][4];
    #pragma unroll
    for (int i = 0; i < 2; i++)
        #pragma unroll
        for (int j = 0; j < 4; j++)
            #pragma unroll
            for (int r = 0; r < 4; r++) acc[i][j][r] = 0.f;

    /* ldmatrix source addresses (bytes) */
    const int a_row = (lane & 15);             /* m within 16-tile  */
    const int a_koff = (lane >> 4) * 4;        /* +16B for k8..15   */
    const int b_row = (lane & 7) + ((lane >> 4) << 3);  /* n within 16 */
    const int b_koff = ((lane >> 3) & 1) * 4;  /* +16B for k8..15   */

    for (int c = 0; c < 3; c++) {
        const int k0 = c * 64;

        /* A: pre-split bf16 weights -> SMEM [64m][32 kpairs], stride ASTR */
        #pragma unroll
        for (int i = tid; i < 2048; i += 256) {
            int m  = i >> 5;
            int kp = i & 31;
            sm[SA_HI + m*ASTR + kp] =
                *(const uint32_t*)&Wh[(m0 + m)*CDIM + k0 + 2*kp];
            sm[SA_LO + m*ASTR + kp] =
                *(const uint32_t*)&Wl[(m0 + m)*CDIM + k0 + 2*kp];
        }
        /* B: fp32 X transpose+split -> SMEM [128n][32 kpairs].
         * Thread owns (n, 8-k group): coalesced LDG (lane = n),
         * one uint4 STS per buffer.                                  */
        #pragma unroll
        for (int it = 0; it < 4; it++) {
            int id = tid + 256*it;
            int n  = id & 127;
            int kg = id >> 7;                  /* 0..7 */
            const float* xp = Xb + (size_t)(k0 + 8*kg) * HW + n0 + n;
            uint32_t hi[4], lo[4];
            #pragma unroll
            for (int j = 0; j < 4; j++) {
                float x0 = xp[(size_t)(2*j)   * HW];
                float x1 = xp[(size_t)(2*j+1) * HW];
                __nv_bfloat16 h0 = __float2bfloat16(x0);
                __nv_bfloat16 h1 = __float2bfloat16(x1);
                __nv_bfloat16 l0 = __float2bfloat16(x0 - __bfloat162float(h0));
                __nv_bfloat16 l1 = __float2bfloat16(x1 - __bfloat162float(h1));
                hi[j] = (uint32_t)__bfloat16_as_ushort(h0)
                      | ((uint32_t)__bfloat16_as_ushort(h1) << 16);
                lo[j] = (uint32_t)__bfloat16_as_ushort(l0)
                      | ((uint32_t)__bfloat16_as_ushort(l1) << 16);
            }
            *(uint4*)&sm[SB_HI + n*ASTR + kg*4] = make_uint4(hi[0],hi[1],hi[2],hi[3]);
            *(uint4*)&sm[SB_LO + n*ASTR + kg*4] = make_uint4(lo[0],lo[1],lo[2],lo[3]);
        }
        __syncthreads();

        #pragma unroll
        for (int s = 0; s < 4; s++) {
            uint32_t ah[2][4], al[2][4], bh[2][4], bl[2][4];
            #pragma unroll
            for (int mf = 0; mf < 2; mf++) {
                uint32_t off = ((wm*32 + mf*16 + a_row)*ASTR + s*8 + a_koff) * 4;
                ldm_x4(ah[mf], sbase + SA_HI*4 + off);
                ldm_x4(al[mf], sbase + SA_LO*4 + off);
            }
            #pragma unroll
            for (int np = 0; np < 2; np++) {   /* n-octet pair: nf 2np, 2np+1 */
                uint32_t off = ((wn*32 + np*16 + b_row)*ASTR + s*8 + b_koff) * 4;
                ldm_x4(bh[np], sbase + SB_HI*4 + off);
                ldm_x4(bl[np], sbase + SB_LO*4 + off);
            }
            #pragma unroll
            for (int mf = 0; mf < 2; mf++)
                #pragma unroll
                for (int nf = 0; nf < 4; nf++) {
                    const uint32_t* pbh = &bh[nf>>1][(nf&1)*2];
                    const uint32_t* pbl = &bl[nf>>1][(nf&1)*2];
                    mma_bf16(acc[mf][nf], ah[mf], pbh);
                    mma_bf16(acc[mf][nf], ah[mf], pbl);
                    mma_bf16(acc[mf][nf], al[mf], pbh);
                }
        }
        __syncthreads();
    }

    /* epilogue: c0,c1 -> (row, col..col+1); c2,c3 -> row+8 */
    #pragma unroll
    for (int mf = 0; mf < 2; mf++) {
        int mr = m0 + wm*32 + mf*16 + grp;
        float bz0 = __ldg(&bias[mr]);
        float bz1 = __ldg(&bias[mr + 8]);
        #pragma unroll
        for (int nf = 0; nf < 4; nf++) {
            int n = n0 + wn*32 + nf*8 + tig*2;
            *(float2*)&Yb[(size_t)mr * HW + n] =
                make_float2(acc[mf][nf][0] + bz0, acc[mf][nf][1] + bz0);
            *(float2*)&Yb[(size_t)(mr + 8) * HW + n] =
                make_float2(acc[mf][nf][2] + bz1, acc[mf][nf][3] + bz1);
        }
    }
}

/* ------------------------------------------------------------------ */
/* Fused raw logits (QP . KP^T over n) + row sum-of-squares.           */
/* ------------------------------------------------------------------ */
__global__ void __launch_bounds__(256)
attn_kernel(const float* __restrict__ qp, const float* __restrict__ kp)
{
    const int bh   = blockIdx.x;
    const int ch   = blockIdx.y;
    const int warp = threadIdx.x >> 5;
    const int lane = threadIdx.x & 31;
    const int b  = bh / HEADS;
    const int hh = bh % HEADS;

    const float* Q = qp + (size_t)(b*CDIM + hh*CH) * HW;
    const float* K = kp + (size_t)(b*CDIM + hh*CH) * HW;
    const int c0 = warp * 4;
    const int n0 = ch * ATT_CHUNK;

    float acc[4][32];
    #pragma unroll
    for (int i = 0; i < 4; i++)
        #pragma unroll
        for (int d = 0; d < 32; d++) acc[i][d] = 0.f;
    float qs[4] = {0.f,0.f,0.f,0.f};
    float ks[4] = {0.f,0.f,0.f,0.f};

    for (int n = n0 + lane; n < n0 + ATT_CHUNK; n += 32) {
        float qv[4];
        #pragma unroll
        for (int i = 0; i < 4; i++) {
            qv[i] = Q[(size_t)(c0 + i) * HW + n];
            qs[i] += qv[i] * qv[i];
        }
        #pragma unroll
        for (int i = 0; i < 4; i++) {
            float kc = K[(size_t)(c0 + i) * HW + n];
            ks[i] += kc * kc;
        }
        #pragma unroll
        for (int d = 0; d < 32; d++) {
            float kv = K[(size_t)d * HW + n];
            #pragma unroll
            for (int i = 0; i < 4; i++) acc[i][d] += qv[i] * kv;
        }
    }

    #pragma unroll
    for (int i = 0; i < 4; i++) {
        float out = 0.f;
        #pragma unroll
        for (int d = 0; d < 32; d++) {
            float v = acc[i][d];
            v += __shfl_xor_sync(0xffffffffu, v, 16);
            v += __shfl_xor_sync(0xffffffffu, v, 8);
            v += __shfl_xor_sync(0xffffffffu, v, 4);
            v += __shfl_xor_sync(0xffffffffu, v, 2);
            v += __shfl_xor_sync(0xffffffffu, v, 1);
            if (lane == d) out = v;
        }
        atomicAdd(&g_attn[bh*CH*CH + (c0 + i)*CH + lane], out);
    }

    #pragma unroll
    for (int i = 0; i < 4; i++) {
        float vq = qs[i], vk = ks[i];
        vq += __shfl_xor_sync(0xffffffffu, vq, 16);
        vq += __shfl_xor_sync(0xffffffffu, vq, 8);
        vq += __shfl_xor_sync(0xffffffffu, vq, 4);
        vq += __shfl_xor_sync(0xffffffffu, vq, 2);
        vq += __shfl_xor_sync(0xffffffffu, vq, 1);
        vk += __shfl_xor_sync(0xffffffffu, vk, 16);
        vk += __shfl_xor_sync(0xffffffffu, vk, 8);
        vk += __shfl_xor_sync(0xffffffffu, vk, 4);
        vk += __shfl_xor_sync(0xffffffffu, vk, 2);
        vk += __shfl_xor_sync(0xffffffffu, vk, 1);
        if (lane == 0) {
            int row = b*CDIM + hh*CH + c0 + i;
            atomicAdd(&g_ss[row], vq);
            atomicAdd(&g_ss[NROWS + row], vk);
        }
    }
}

/* ------------------------------------------------------------------ */
__global__ void softmax_kernel(const float* __restrict__ temp)
{
    const int bh = blockIdx.x;
    const int b  = bh / HEADS;
    const int hh = bh % HEADS;
    const int c  = threadIdx.y;
    const int d  = threadIdx.x;

    const int rowq = b*CDIM + hh*CH + c;
    const int rowk = b*CDIM + hh*CH + d;
    float rq = 1.f / fmaxf(sqrtf(g_ss[rowq]), 1e-12f);
    float rk = 1.f / fmaxf(sqrtf(g_ss[NROWS + rowk]), 1e-12f);

    int idx = bh*CH*CH + c*CH + d;
    float v = g_attn[idx] * rq * rk * temp[hh];

    float m = v;
    m = fmaxf(m, __shfl_xor_sync(0xffffffffu, m, 16));
    m = fmaxf(m, __shfl_xor_sync(0xffffffffu, m, 8));
    m = fmaxf(m, __shfl_xor_sync(0xffffffffu, m, 4));
    m = fmaxf(m, __shfl_xor_sync(0xffffffffu, m, 2));
    m = fmaxf(m, __shfl_xor_sync(0xffffffffu, m, 1));
    float e = __expf(v - m);
    float s = e;
    s += __shfl_xor_sync(0xffffffffu, s, 16);
    s += __shfl_xor_sync(0xffffffffu, s, 8);
    s += __shfl_xor_sync(0xffffffffu, s, 4);
    s += __shfl_xor_sync(0xffffffffu, s, 2);
    s += __shfl_xor_sync(0xffffffffu, s, 1);
    g_attn[idx] = e / s;
}

/* ------------------------------------------------------------------ */
/* Fold attention probs into Wo; emit bf16 hi/lo directly.             */
/* ------------------------------------------------------------------ */
__global__ void weff_kernel(const float* __restrict__ wo)
{
    const int b   = blockIdx.y;
    const int idx = blockIdx.x * 256 + threadIdx.x;
    const int o   = idx / CDIM;
    const int dg  = idx % CDIM;
    const int h   = dg / CH;
    const int dc  = dg % CH;

    const float* P    = g_attn + ((b*HEADS + h)*CH)*CH;
    const float* wrow = wo + o*CDIM + h*CH;
    float s = 0.f;
    #pragma unroll
    for (int c = 0; c < CH; c++)
        s += wrow[c] * P[c*CH + dc];

    size_t off = (size_t)b*WSZ + o*CDIM + dg;
    __nv_bfloat16 hw = __float2bfloat16(s);
    g_weffh[off] = hw;
    g_weffl[off] = __float2bfloat16(s - __bfloat162float(hw));
}

/* ------------------------------------------------------------------ */
extern "C" void kernel_launch(void* const* d_in, const int* in_sizes, int n_in,
                              void* d_out, int out_size)
{
    const float* q    = (const float*)d_in[0];
    const float* k    = (const float*)d_in[1];
    const float* v    = (const float*)d_in[2];
    const float* wq   = (const float*)d_in[3];
    const float* bq   = (const float*)d_in[4];
    const float* wk   = (const float*)d_in[5];
    const float* bk   = (const float*)d_in[6];
    const float* wv   = (const float*)d_in[7];
    const float* bv   = (const float*)d_in[8];
    const float* wo   = (const float*)d_in[9];
    const float* bo   = (const float*)d_in[10];
    const float* temp = (const float*)d_in[11];

    float *qp, *kp, *vp;
    __nv_bfloat16 *wh, *wl, *weh, *wel;
    cudaGetSymbolAddress((void**)&qp,  g_qp);
    cudaGetSymbolAddress((void**)&kp,  g_kp);
    cudaGetSymbolAddress((void**)&vp,  g_vp);
    cudaGetSymbolAddress((void**)&wh,  g_wh);
    cudaGetSymbolAddress((void**)&wl,  g_wl);
    cudaGetSymbolAddress((void**)&weh, g_weffh);
    cudaGetSymbolAddress((void**)&wel, g_weffl);

    const int smem_bytes = S_WORDS * 4;
    cudaFuncSetAttribute(gemm_bf16, cudaFuncAttributeMaxDynamicSharedMemorySize,
                         smem_bytes);

    zero_kernel<<<(NBH*CH*CH + 255)/256, 256>>>();
    prep_w<<<(3*WSZ + 255)/256, 256>>>(wq, wk, wv);

    dim3 gg(HW/128, CDIM/64, BATCH);
    gemm_bf16<<<gg, 256, smem_bytes>>>(q, wh + 0*WSZ, wl + 0*WSZ, bq, qp, 0);
    gemm_bf16<<<gg, 256, smem_bytes>>>(k, wh + 1*WSZ, wl + 1*WSZ, bk, kp, 0);
    gemm_bf16<<<gg, 256, smem_bytes>>>(v, wh + 2*WSZ, wl + 2*WSZ, bv, vp, 0);

    attn_kernel<<<dim3(NBH, ATT_CHUNKS), 256>>>(qp, kp);
    softmax_kernel<<<NBH, dim3(32, 32)>>>(temp);
    weff_kernel<<<dim3((CDIM*CDIM)/256, BATCH), 256>>>(wo);

    gemm_bf16<<<gg, 256, smem_bytes>>>(vp, weh, wel, bo, (float*)d_out, WSZ);
}

// round 10
// speedup vs baseline: 3.2756x; 1.0307x over previous
#include <cuda_runtime.h>
#include <cuda_bf16.h>
#include <cstdint>

#define HW    16384
#define BATCH 8
#define CDIM  192
#define HEADS 6
#define CH    32
#define NROWS (BATCH*CDIM)      /* 1536 */
#define NBH   (BATCH*HEADS)     /* 48   */
#define ATT_CHUNKS 8
#define ATT_CHUNK  (HW/ATT_CHUNKS)
#define WSZ   (CDIM*CDIM)       /* 36864 */
#define NSPLIT 6                /* n-split CTAs per (m,b): 6*3*8 = 144 CTAs */

/* ------------------------------------------------------------------ */
/* Scratch (device globals: no allocations allowed)                    */
/* ------------------------------------------------------------------ */
__device__ float g_qp[BATCH*CDIM*HW];
__device__ float g_kp[BATCH*CDIM*HW];
__device__ float g_vp[BATCH*CDIM*HW];
__device__ float g_attn[NBH*CH*CH];
__device__ float g_ss[2*NROWS];
__device__ __nv_bfloat16 g_wh[3*WSZ];
__device__ __nv_bfloat16 g_wl[3*WSZ];
__device__ __nv_bfloat16 g_weffh[BATCH*WSZ];
__device__ __nv_bfloat16 g_weffl[BATCH*WSZ];

/* ------------------------------------------------------------------ */
__global__ void zero_kernel() {
    int i = blockIdx.x * 256 + threadIdx.x;
    if (i < NBH*CH*CH) g_attn[i] = 0.f;
    if (i < 2*NROWS)   g_ss[i]   = 0.f;
}

__global__ void prep_w(const float* __restrict__ wq,
                       const float* __restrict__ wk,
                       const float* __restrict__ wv)
{
    int i = blockIdx.x * 256 + threadIdx.x;
    if (i >= 3*WSZ) return;
    const float* src = (i < WSZ) ? wq : (i < 2*WSZ ? wk : wv);
    float x = src[i % WSZ];
    __nv_bfloat16 h = __float2bfloat16(x);
    g_wh[i] = h;
    g_wl[i] = __float2bfloat16(x - __bfloat162float(h));
}

/* ------------------------------------------------------------------ */
/* Persistent, cp.async-pipelined bf16-split tensor-core conv1x1.
 * CTA owns (m-block 64, batch); loops n-tiles of 128.
 * A (full K=192 hi/lo) staged once. Per chunk (K=64): raw fp32 X is
 * cp.async'd into stage[next] during the MMA phase of the current
 * chunk; convert reads stage from SMEM.                               */
/* ------------------------------------------------------------------ */
/* SMEM word map */
#define ASTR  100                      /* A row stride (words), full-K 96 + pad */
#define BSTR  36                       /* B row stride (words), 32 kpairs + pad */
#define SA_HI 0
#define SA_LO (64*ASTR)                /* 6400  */
#define SB_HI (2*64*ASTR)              /* 12800 */
#define SB_LO (2*64*ASTR + 128*BSTR)   /* 17408 */
#define STG0  (2*64*ASTR + 2*128*BSTR) /* 22016 */
#define STGSZ (64*128)                 /* 8192 words per stage buffer */
#define S_WORDS (STG0 + 2*STGSZ)       /* 38400 words = 153600 B */

__device__ __forceinline__ uint32_t smem_u32(const void* p) {
    uint32_t a;
    asm("{ .reg .u64 t; cvta.to.shared.u64 t, %1; cvt.u32.u64 %0, t; }"
        : "=r"(a) : "l"(p));
    return a;
}
__device__ __forceinline__ void cp16(uint32_t saddr, const void* g) {
    asm volatile("cp.async.cg.shared.global [%0], [%1], 16;"
                 :: "r"(saddr), "l"(g));
}
#define CP_COMMIT() asm volatile("cp.async.commit_group;" ::: "memory")
#define CP_WAIT0()  asm volatile("cp.async.wait_group 0;" ::: "memory")

__device__ __forceinline__ void ldm_x4(uint32_t* r, uint32_t addr) {
    asm volatile("ldmatrix.sync.aligned.m8n8.x4.shared.b16 {%0,%1,%2,%3}, [%4];"
        : "=r"(r[0]), "=r"(r[1]), "=r"(r[2]), "=r"(r[3]) : "r"(addr));
}
__device__ __forceinline__ void mma_bf16(float* c, const uint32_t* a, const uint32_t* b) {
    asm volatile(
        "mma.sync.aligned.m16n8k16.row.col.f32.bf16.bf16.f32 "
        "{%0,%1,%2,%3}, {%4,%5,%6,%7}, {%8,%9}, {%0,%1,%2,%3};"
        : "+f"(c[0]), "+f"(c[1]), "+f"(c[2]), "+f"(c[3])
        : "r"(a[0]), "r"(a[1]), "r"(a[2]), "r"(a[3]), "r"(b[0]), "r"(b[1]));
}

__global__ void __launch_bounds__(256, 1)
gemm_bf16(const float* __restrict__ X,
          const __nv_bfloat16* __restrict__ Whi,
          const __nv_bfloat16* __restrict__ Wlo,
          const float* __restrict__ bias,
          float* __restrict__ Y, int wstride)
{
    extern __shared__ uint32_t sm[];
    const uint32_t sbase = smem_u32(sm);

    const int tid  = threadIdx.x;
    const int wid  = tid >> 5;
    const int lane = tid & 31;
    const int grp  = lane >> 2;
    const int tig  = lane & 3;
    const int wm   = wid & 1;
    const int wn   = wid >> 1;

    const int m0 = blockIdx.y * 64;
    const int b  = blockIdx.z;

    const float* Xb = X + (size_t)b * CDIM * HW;
    float*       Yb = Y + (size_t)b * CDIM * HW;
    const __nv_bfloat16* Wh = Whi + (size_t)b * wstride;
    const __nv_bfloat16* Wl = Wlo + (size_t)b * wstride;

    /* A: full-K hi/lo staged once (64 m x 96 kpairs, stride 100) */
    for (int i = tid; i < 64*96; i += 256) {
        int m = i / 96, kp = i % 96;
        sm[SA_HI + m*ASTR + kp] = *(const uint32_t*)&Wh[(m0 + m)*CDIM + 2*kp];
        sm[SA_LO + m*ASTR + kp] = *(const uint32_t*)&Wl[(m0 + m)*CDIM + 2*kp];
    }

    /* ldmatrix addressing */
    const int a_row  = lane & 15;
    const int a_koff = (lane >> 4) * 4;
    const int b_row  = (lane & 7) + ((lane >> 4) << 3);
    const int b_koff = ((lane >> 3) & 1) * 4;

    /* bias (fixed per CTA) */
    float bz[2][2];
    #pragma unroll
    for (int mf = 0; mf < 2; mf++) {
        bz[mf][0] = __ldg(&bias[m0 + wm*32 + mf*16 + grp]);
        bz[mf][1] = __ldg(&bias[m0 + wm*32 + mf*16 + grp + 8]);
    }

    float acc[2][4][4];
    #pragma unroll
    for (int i = 0; i < 2; i++)
        #pragma unroll
        for (int j = 0; j < 4; j++)
            #pragma unroll
            for (int r = 0; r < 4; r++) acc[i][j][r] = 0.f;

    /* pipeline prologue: stage[0] <- (tile0, chunk0) */
    {
        const int n0 = blockIdx.x * 128;
        #pragma unroll
        for (int r = 0; r < 8; r++) {
            int u = tid + 256*r;
            int k = u >> 5, seg = u & 31;
            cp16(sbase + (STG0 + k*128 + seg*4)*4,
                 Xb + (size_t)k * HW + n0 + seg*4);
        }
        CP_COMMIT();
    }

    int cur = 0;
    for (int tile = blockIdx.x; tile < HW/128; tile += NSPLIT) {
        const int n0 = tile * 128;
        for (int c = 0; c < 3; c++) {
            CP_WAIT0();
            __syncthreads();

            /* convert stage[cur] (fp32) -> operand B (bf16 hi/lo) */
            {
                const uint32_t st = STG0 + cur*STGSZ;
                #pragma unroll
                for (int it2 = 0; it2 < 4; it2++) {
                    int id = tid + 256*it2;
                    int nn = id & 127;
                    int kg = id >> 7;
                    uint32_t hi[4], lo[4];
                    #pragma unroll
                    for (int j = 0; j < 4; j++) {
                        float x0 = __uint_as_float(sm[st + (8*kg + 2*j)*128 + nn]);
                        float x1 = __uint_as_float(sm[st + (8*kg + 2*j+1)*128 + nn]);
                        __nv_bfloat16 h0 = __float2bfloat16(x0);
                        __nv_bfloat16 h1 = __float2bfloat16(x1);
                        __nv_bfloat16 l0 = __float2bfloat16(x0 - __bfloat162float(h0));
                        __nv_bfloat16 l1 = __float2bfloat16(x1 - __bfloat162float(h1));
                        hi[j] = (uint32_t)__bfloat16_as_ushort(h0)
                              | ((uint32_t)__bfloat16_as_ushort(h1) << 16);
                        lo[j] = (uint32_t)__bfloat16_as_ushort(l0)
                              | ((uint32_t)__bfloat16_as_ushort(l1) << 16);
                    }
                    *(uint4*)&sm[SB_HI + nn*BSTR + kg*4] = make_uint4(hi[0],hi[1],hi[2],hi[3]);
                    *(uint4*)&sm[SB_LO + nn*BSTR + kg*4] = make_uint4(lo[0],lo[1],lo[2],lo[3]);
                }
            }

            /* prefetch next chunk into stage[cur^1] (flies during MMA) */
            {
                int nc = c + 1, nt = tile;
                if (nc == 3) { nc = 0; nt = tile + NSPLIT; }
                if (nt < HW/128) {
                    const int nn0 = nt * 128;
                    const int nk0 = nc * 64;
                    const uint32_t st2 = STG0 + (cur^1)*STGSZ;
                    #pragma unroll
                    for (int r = 0; r < 8; r++) {
                        int u = tid + 256*r;
                        int k = u >> 5, seg = u & 31;
                        cp16(sbase + (st2 + k*128 + seg*4)*4,
                             Xb + (size_t)(nk0 + k) * HW + nn0 + seg*4);
                    }
                }
                CP_COMMIT();
            }
            __syncthreads();

            /* MMA over chunk c */
            #pragma unroll
            for (int s = 0; s < 4; s++) {
                uint32_t ah[2][4], al[2][4], bh[2][4], bl[2][4];
                #pragma unroll
                for (int mf = 0; mf < 2; mf++) {
                    uint32_t off = ((wm*32 + mf*16 + a_row)*ASTR + c*32 + s*8 + a_koff) * 4;
                    ldm_x4(ah[mf], sbase + SA_HI*4 + off);
                    ldm_x4(al[mf], sbase + SA_LO*4 + off);
                }
                #pragma unroll
                for (int np = 0; np < 2; np++) {
                    uint32_t off = ((wn*32 + np*16 + b_row)*BSTR + s*8 + b_koff) * 4;
                    ldm_x4(bh[np], sbase + SB_HI*4 + off);
                    ldm_x4(bl[np], sbase + SB_LO*4 + off);
                }
                #pragma unroll
                for (int mf = 0; mf < 2; mf++)
                    #pragma unroll
                    for (int nf = 0; nf < 4; nf++) {
                        const uint32_t* pbh = &bh[nf>>1][(nf&1)*2];
                        const uint32_t* pbl = &bl[nf>>1][(nf&1)*2];
                        mma_bf16(acc[mf][nf], ah[mf], pbh);
                        mma_bf16(acc[mf][nf], ah[mf], pbl);
                        mma_bf16(acc[mf][nf], al[mf], pbh);
                    }
            }
            cur ^= 1;
        }

        /* epilogue for this tile */
        #pragma unroll
        for (int mf = 0; mf < 2; mf++) {
            int mr = m0 + wm*32 + mf*16 + grp;
            #pragma unroll
            for (int nf = 0; nf < 4; nf++) {
                int n = n0 + wn*32 + nf*8 + tig*2;
                *(float2*)&Yb[(size_t)mr * HW + n] =
                    make_float2(acc[mf][nf][0] + bz[mf][0], acc[mf][nf][1] + bz[mf][0]);
                *(float2*)&Yb[(size_t)(mr + 8) * HW + n] =
                    make_float2(acc[mf][nf][2] + bz[mf][1], acc[mf][nf][3] + bz[mf][1]);
                acc[mf][nf][0] = acc[mf][nf][1] = acc[mf][nf][2] = acc[mf][nf][3] = 0.f;
            }
        }
    }
}

/* ------------------------------------------------------------------ */
/* Fused raw logits + row sum-of-squares, float4-vectorized.           */
/* ------------------------------------------------------------------ */
__global__ void __launch_bounds__(256)
attn_kernel(const float* __restrict__ qp, const float* __restrict__ kp)
{
    const int bh   = blockIdx.x;
    const int ch   = blockIdx.y;
    const int warp = threadIdx.x >> 5;
    const int lane = threadIdx.x & 31;
    const int b  = bh / HEADS;
    const int hh = bh % HEADS;

    const float* Q = qp + (size_t)(b*CDIM + hh*CH) * HW;
    const float* K = kp + (size_t)(b*CDIM + hh*CH) * HW;
    const int c0 = warp * 4;

    float acc[4][32];
    #pragma unroll
    for (int i = 0; i < 4; i++)
        #pragma unroll
        for (int d = 0; d < 32; d++) acc[i][d] = 0.f;
    float qs[4] = {0.f,0.f,0.f,0.f};
    float ks[4] = {0.f,0.f,0.f,0.f};

    const int v0 = (ch * ATT_CHUNK) >> 2;          /* float4 index base */
    for (int n = v0 + lane; n < v0 + (ATT_CHUNK >> 2); n += 32) {
        float4 qv[4];
        #pragma unroll
        for (int i = 0; i < 4; i++) {
            qv[i] = ((const float4*)(Q + (size_t)(c0 + i) * HW))[n];
            qs[i] += qv[i].x*qv[i].x + qv[i].y*qv[i].y
                   + qv[i].z*qv[i].z + qv[i].w*qv[i].w;
        }
        #pragma unroll
        for (int i = 0; i < 4; i++) {
            float4 kc = ((const float4*)(K + (size_t)(c0 + i) * HW))[n];
            ks[i] += kc.x*kc.x + kc.y*kc.y + kc.z*kc.z + kc.w*kc.w;
        }
        #pragma unroll
        for (int d = 0; d < 32; d++) {
            float4 kv = ((const float4*)(K + (size_t)d * HW))[n];
            #pragma unroll
            for (int i = 0; i < 4; i++)
                acc[i][d] += qv[i].x*kv.x + qv[i].y*kv.y
                           + qv[i].z*kv.z + qv[i].w*kv.w;
        }
    }

    #pragma unroll
    for (int i = 0; i < 4; i++) {
        float out = 0.f;
        #pragma unroll
        for (int d = 0; d < 32; d++) {
            float v = acc[i][d];
            v += __shfl_xor_sync(0xffffffffu, v, 16);
            v += __shfl_xor_sync(0xffffffffu, v, 8);
            v += __shfl_xor_sync(0xffffffffu, v, 4);
            v += __shfl_xor_sync(0xffffffffu, v, 2);
            v += __shfl_xor_sync(0xffffffffu, v, 1);
            if (lane == d) out = v;
        }
        atomicAdd(&g_attn[bh*CH*CH + (c0 + i)*CH + lane], out);
    }

    #pragma unroll
    for (int i = 0; i < 4; i++) {
        float vq = qs[i], vk = ks[i];
        vq += __shfl_xor_sync(0xffffffffu, vq, 16);
        vq += __shfl_xor_sync(0xffffffffu, vq, 8);
        vq += __shfl_xor_sync(0xffffffffu, vq, 4);
        vq += __shfl_xor_sync(0xffffffffu, vq, 2);
        vq += __shfl_xor_sync(0xffffffffu, vq, 1);
        vk += __shfl_xor_sync(0xffffffffu, vk, 16);
        vk += __shfl_xor_sync(0xffffffffu, vk, 8);
        vk += __shfl_xor_sync(0xffffffffu, vk, 4);
        vk += __shfl_xor_sync(0xffffffffu, vk, 2);
        vk += __shfl_xor_sync(0xffffffffu, vk, 1);
        if (lane == 0) {
            int row = b*CDIM + hh*CH + c0 + i;
            atomicAdd(&g_ss[row], vq);
            atomicAdd(&g_ss[NROWS + row], vk);
        }
    }
}

/* ------------------------------------------------------------------ */
__global__ void softmax_kernel(const float* __restrict__ temp)
{
    const int bh = blockIdx.x;
    const int b  = bh / HEADS;
    const int hh = bh % HEADS;
    const int c  = threadIdx.y;
    const int d  = threadIdx.x;

    const int rowq = b*CDIM + hh*CH + c;
    const int rowk = b*CDIM + hh*CH + d;
    float rq = 1.f / fmaxf(sqrtf(g_ss[rowq]), 1e-12f);
    float rk = 1.f / fmaxf(sqrtf(g_ss[NROWS + rowk]), 1e-12f);

    int idx = bh*CH*CH + c*CH + d;
    float v = g_attn[idx] * rq * rk * temp[hh];

    float m = v;
    m = fmaxf(m, __shfl_xor_sync(0xffffffffu, m, 16));
    m = fmaxf(m, __shfl_xor_sync(0xffffffffu, m, 8));
    m = fmaxf(m, __shfl_xor_sync(0xffffffffu, m, 4));
    m = fmaxf(m, __shfl_xor_sync(0xffffffffu, m, 2));
    m = fmaxf(m, __shfl_xor_sync(0xffffffffu, m, 1));
    float e = __expf(v - m);
    float s = e;
    s += __shfl_xor_sync(0xffffffffu, s, 16);
    s += __shfl_xor_sync(0xffffffffu, s, 8);
    s += __shfl_xor_sync(0xffffffffu, s, 4);
    s += __shfl_xor_sync(0xffffffffu, s, 2);
    s += __shfl_xor_sync(0xffffffffu, s, 1);
    g_attn[idx] = e / s;
}

/* ------------------------------------------------------------------ */
__global__ void weff_kernel(const float* __restrict__ wo)
{
    const int b   = blockIdx.y;
    const int idx = blockIdx.x * 256 + threadIdx.x;
    const int o   = idx / CDIM;
    const int dg  = idx % CDIM;
    const int h   = dg / CH;
    const int dc  = dg % CH;

    const float* P    = g_attn + ((b*HEADS + h)*CH)*CH;
    const float* wrow = wo + o*CDIM + h*CH;
    float s = 0.f;
    #pragma unroll
    for (int c = 0; c < CH; c++)
        s += wrow[c] * P[c*CH + dc];

    size_t off = (size_t)b*WSZ + o*CDIM + dg;
    __nv_bfloat16 hw = __float2bfloat16(s);
    g_weffh[off] = hw;
    g_weffl[off] = __float2bfloat16(s - __bfloat162float(hw));
}

/* ------------------------------------------------------------------ */
extern "C" void kernel_launch(void* const* d_in, const int* in_sizes, int n_in,
                              void* d_out, int out_size)
{
    const float* q    = (const float*)d_in[0];
    const float* k    = (const float*)d_in[1];
    const float* v    = (const float*)d_in[2];
    const float* wq   = (const float*)d_in[3];
    const float* bq   = (const float*)d_in[4];
    const float* wk   = (const float*)d_in[5];
    const float* bk   = (const float*)d_in[6];
    const float* wv   = (const float*)d_in[7];
    const float* bv   = (const float*)d_in[8];
    const float* wo   = (const float*)d_in[9];
    const float* bo   = (const float*)d_in[10];
    const float* temp = (const float*)d_in[11];

    float *qp, *kp, *vp;
    __nv_bfloat16 *wh, *wl, *weh, *wel;
    cudaGetSymbolAddress((void**)&qp,  g_qp);
    cudaGetSymbolAddress((void**)&kp,  g_kp);
    cudaGetSymbolAddress((void**)&vp,  g_vp);
    cudaGetSymbolAddress((void**)&wh,  g_wh);
    cudaGetSymbolAddress((void**)&wl,  g_wl);
    cudaGetSymbolAddress((void**)&weh, g_weffh);
    cudaGetSymbolAddress((void**)&wel, g_weffl);

    const int smem_bytes = S_WORDS * 4;
    cudaFuncSetAttribute(gemm_bf16, cudaFuncAttributeMaxDynamicSharedMemorySize,
                         smem_bytes);

    zero_kernel<<<(NBH*CH*CH + 255)/256, 256>>>();
    prep_w<<<(3*WSZ + 255)/256, 256>>>(wq, wk, wv);

    dim3 gg(NSPLIT, CDIM/64, BATCH);
    gemm_bf16<<<gg, 256, smem_bytes>>>(q, wh + 0*WSZ, wl + 0*WSZ, bq, qp, 0);
    gemm_bf16<<<gg, 256, smem_bytes>>>(k, wh + 1*WSZ, wl + 1*WSZ, bk, kp, 0);
    gemm_bf16<<<gg, 256, smem_bytes>>>(v, wh + 2*WSZ, wl + 2*WSZ, bv, vp, 0);

    attn_kernel<<<dim3(NBH, ATT_CHUNKS), 256>>>(qp, kp);
    softmax_kernel<<<NBH, dim3(32, 32)>>>(temp);
    weff_kernel<<<dim3((CDIM*CDIM)/256, BATCH), 256>>>(wo);

    gemm_bf16<<<gg, 256, smem_bytes>>>(vp, weh, wel, bo, (float*)d_out, WSZ);
}

// round 12
// speedup vs baseline: 3.6403x; 1.1113x over previous
#include <cuda_runtime.h>
#include <cuda_bf16.h>
#include <cstdint>

#define HW    16384
#define BATCH 8
#define CDIM  192
#define HEADS 6
#define CH    32
#define NROWS (BATCH*CDIM)      /* 1536 */
#define NBH   (BATCH*HEADS)     /* 48   */
#define ATT_CHUNKS 8
#define ATT_CHUNK  (HW/ATT_CHUNKS)
#define WSZ   (CDIM*CDIM)       /* 36864 */

/* ------------------------------------------------------------------ */
/* Scratch (device globals: no allocations allowed)                    */
/* ------------------------------------------------------------------ */
__device__ float g_qp[BATCH*CDIM*HW];
__device__ float g_kp[BATCH*CDIM*HW];
__device__ float g_vp[BATCH*CDIM*HW];
__device__ float g_attn[NBH*CH*CH];
__device__ float g_ss[2*NROWS];
__device__ __nv_bfloat16 g_wh[3*WSZ];
__device__ __nv_bfloat16 g_wl[3*WSZ];
__device__ __nv_bfloat16 g_weffh[BATCH*WSZ];
__device__ __nv_bfloat16 g_weffl[BATCH*WSZ];

/* ------------------------------------------------------------------ */
__global__ void zero_kernel() {
    int i = blockIdx.x * 256 + threadIdx.x;
    if (i < NBH*CH*CH) g_attn[i] = 0.f;
    if (i < 2*NROWS)   g_ss[i]   = 0.f;
}

__global__ void prep_w(const float* __restrict__ wq,
                       const float* __restrict__ wk,
                       const float* __restrict__ wv)
{
    int i = blockIdx.x * 256 + threadIdx.x;
    if (i >= 3*WSZ) return;
    const float* src = (i < WSZ) ? wq : (i < 2*WSZ ? wk : wv);
    float x = src[i % WSZ];
    __nv_bfloat16 h = __float2bfloat16(x);
    g_wh[i] = h;
    g_wl[i] = __float2bfloat16(x - __bfloat162float(h));
}

/* ------------------------------------------------------------------ */
/* bf16-split tensor-core conv1x1, ldmatrix + mma.sync.m16n8k16.
 * CTA: 64(M=cout) x 128(N=spatial), 2 CTAs/SM; K=192 in 3 chunks.
 * Raw fp32 X for chunk c+1 is cp.async'd into a single SMEM stage
 * during the MMA phase of chunk c; convert reads the stage (LDS).    */
/* ------------------------------------------------------------------ */
/* SMEM word map */
#define ASTR  36
#define BSTR  36
#define SA_HI 0
#define SA_LO (64*ASTR)                 /* 2304  */
#define SB_HI (2*64*ASTR)               /* 4608  */
#define SB_LO (2*64*ASTR + 128*BSTR)    /* 9216  */
#define STG   (2*64*ASTR + 2*128*BSTR)  /* 13824 */
#define S_WORDS (STG + 64*128)          /* 22016 words = 88064 B */

__device__ __forceinline__ uint32_t smem_u32(const void* p) {
    uint32_t a;
    asm("{ .reg .u64 t; cvta.to.shared.u64 t, %1; cvt.u32.u64 %0, t; }"
        : "=r"(a) : "l"(p));
    return a;
}
__device__ __forceinline__ void cp16(uint32_t saddr, const void* g) {
    asm volatile("cp.async.cg.shared.global [%0], [%1], 16;"
                 :: "r"(saddr), "l"(g));
}
#define CP_COMMIT() asm volatile("cp.async.commit_group;" ::: "memory")
#define CP_WAIT0()  asm volatile("cp.async.wait_group 0;" ::: "memory")

__device__ __forceinline__ void ldm_x4(uint32_t* r, uint32_t addr) {
    asm volatile("ldmatrix.sync.aligned.m8n8.x4.shared.b16 {%0,%1,%2,%3}, [%4];"
        : "=r"(r[0]), "=r"(r[1]), "=r"(r[2]), "=r"(r[3]) : "r"(addr));
}
__device__ __forceinline__ void mma_bf16(float* c, const uint32_t* a, const uint32_t* b) {
    asm volatile(
        "mma.sync.aligned.m16n8k16.row.col.f32.bf16.bf16.f32 "
        "{%0,%1,%2,%3}, {%4,%5,%6,%7}, {%8,%9}, {%0,%1,%2,%3};"
        : "+f"(c[0]), "+f"(c[1]), "+f"(c[2]), "+f"(c[3])
        : "r"(a[0]), "r"(a[1]), "r"(a[2]), "r"(a[3]), "r"(b[0]), "r"(b[1]));
}

__global__ void __launch_bounds__(256, 2)
gemm_bf16(const float* __restrict__ X,
          const __nv_bfloat16* __restrict__ Whi,
          const __nv_bfloat16* __restrict__ Wlo,
          const float* __restrict__ bias,
          float* __restrict__ Y, int wstride)
{
    extern __shared__ uint32_t sm[];
    const uint32_t sbase = smem_u32(sm);

    const int tid  = threadIdx.x;
    const int wid  = tid >> 5;
    const int lane = tid & 31;
    const int grp  = lane >> 2;
    const int tig  = lane & 3;
    const int wm   = wid & 1;
    const int wn   = wid >> 1;

    const int n0 = blockIdx.x * 128;
    const int m0 = blockIdx.y * 64;
    const int b  = blockIdx.z;

    const float* Xb = X + (size_t)b * CDIM * HW;
    float*       Yb = Y + (size_t)b * CDIM * HW;
    const __nv_bfloat16* Wh = Whi + (size_t)b * wstride;
    const __nv_bfloat16* Wl = Wlo + (size_t)b * wstride;

    /* ldmatrix addressing */
    const int a_row  = lane & 15;
    const int a_koff = (lane >> 4) * 4;
    const int b_row  = (lane & 7) + ((lane >> 4) << 3);
    const int b_koff = ((lane >> 3) & 1) * 4;

    float acc[2][4][4];
    #pragma unroll
    for (int i = 0; i < 2; i++)
        #pragma unroll
        for (int j = 0; j < 4; j++)
            #pragma unroll
            for (int r = 0; r < 4; r++) acc[i][j][r] = 0.f;

    /* prologue: stage <- chunk 0 raw fp32 (64 k x 128 n) */
    #pragma unroll
    for (int r = 0; r < 8; r++) {
        int u = tid + 256*r;
        int k = u >> 5, seg = u & 31;
        cp16(sbase + (STG + k*128 + seg*4)*4,
             Xb + (size_t)k * HW + n0 + seg*4);
    }
    CP_COMMIT();

    for (int c = 0; c < 3; c++) {
        const int k0 = c * 64;
        CP_WAIT0();
        __syncthreads();     /* stage[c] ready; operand buffers free */

        /* A: chunk weights hi/lo -> SMEM (uint4: 8 bf16 per ld/st) */
        #pragma unroll
        for (int r = 0; r < 2; r++) {
            int i = tid + 256*r;
            int m = i >> 3, kg = i & 7;
            *(uint4*)&sm[SA_HI + m*ASTR + kg*4] =
                *(const uint4*)&Wh[(m0 + m)*CDIM + k0 + 8*kg];
            *(uint4*)&sm[SA_LO + m*ASTR + kg*4] =
                *(const uint4*)&Wl[(m0 + m)*CDIM + k0 + 8*kg];
        }

        /* convert stage (fp32) -> B operand (bf16 hi/lo, ldmatrix-ready) */
        #pragma unroll
        for (int it2 = 0; it2 < 4; it2++) {
            int id = tid + 256*it2;
            int nn = id & 127;
            int kg = id >> 7;
            uint32_t hi[4], lo[4];
            #pragma unroll
            for (int j = 0; j < 4; j++) {
                float x0 = __uint_as_float(sm[STG + (8*kg + 2*j)*128 + nn]);
                float x1 = __uint_as_float(sm[STG + (8*kg + 2*j+1)*128 + nn]);
                __nv_bfloat16 h0 = __float2bfloat16(x0);
                __nv_bfloat16 h1 = __float2bfloat16(x1);
                __nv_bfloat16 l0 = __float2bfloat16(x0 - __bfloat162float(h0));
                __nv_bfloat16 l1 = __float2bfloat16(x1 - __bfloat162float(h1));
                hi[j] = (uint32_t)__bfloat16_as_ushort(h0)
                      | ((uint32_t)__bfloat16_as_ushort(h1) << 16);
                lo[j] = (uint32_t)__bfloat16_as_ushort(l0)
                      | ((uint32_t)__bfloat16_as_ushort(l1) << 16);
            }
            *(uint4*)&sm[SB_HI + nn*BSTR + kg*4] = make_uint4(hi[0],hi[1],hi[2],hi[3]);
            *(uint4*)&sm[SB_LO + nn*BSTR + kg*4] = make_uint4(lo[0],lo[1],lo[2],lo[3]);
        }
        __syncthreads();     /* operands ready; stage fully consumed */

        /* prefetch next chunk into the (now free) stage during MMA */
        if (c < 2) {
            const int nk0 = k0 + 64;
            #pragma unroll
            for (int r = 0; r < 8; r++) {
                int u = tid + 256*r;
                int k = u >> 5, seg = u & 31;
                cp16(sbase + (STG + k*128 + seg*4)*4,
                     Xb + (size_t)(nk0 + k) * HW + n0 + seg*4);
            }
        }
        CP_COMMIT();

        /* MMA over chunk c */
        #pragma unroll
        for (int s = 0; s < 4; s++) {
            uint32_t ah[2][4], al[2][4], bh[2][4], bl[2][4];
            #pragma unroll
            for (int mf = 0; mf < 2; mf++) {
                uint32_t off = ((wm*32 + mf*16 + a_row)*ASTR + s*8 + a_koff) * 4;
                ldm_x4(ah[mf], sbase + SA_HI*4 + off);
                ldm_x4(al[mf], sbase + SA_LO*4 + off);
            }
            #pragma unroll
            for (int np = 0; np < 2; np++) {
                uint32_t off = ((wn*32 + np*16 + b_row)*BSTR + s*8 + b_koff) * 4;
                ldm_x4(bh[np], sbase + SB_HI*4 + off);
                ldm_x4(bl[np], sbase + SB_LO*4 + off);
            }
            #pragma unroll
            for (int mf = 0; mf < 2; mf++)
                #pragma unroll
                for (int nf = 0; nf < 4; nf++) {
                    const uint32_t* pbh = &bh[nf>>1][(nf&1)*2];
                    const uint32_t* pbl = &bl[nf>>1][(nf&1)*2];
                    mma_bf16(acc[mf][nf], ah[mf], pbh);
                    mma_bf16(acc[mf][nf], ah[mf], pbl);
                    mma_bf16(acc[mf][nf], al[mf], pbh);
                }
        }
        __syncthreads();     /* done with operand buffers before restage */
    }

    /* epilogue */
    #pragma unroll
    for (int mf = 0; mf < 2; mf++) {
        int mr = m0 + wm*32 + mf*16 + grp;
        float bz0 = __ldg(&bias[mr]);
        float bz1 = __ldg(&bias[mr + 8]);
        #pragma unroll
        for (int nf = 0; nf < 4; nf++) {
            int n = n0 + wn*32 + nf*8 + tig*2;
            *(float2*)&Yb[(size_t)mr * HW + n] =
                make_float2(acc[mf][nf][0] + bz0, acc[mf][nf][1] + bz0);
            *(float2*)&Yb[(size_t)(mr + 8) * HW + n] =
                make_float2(acc[mf][nf][2] + bz1, acc[mf][nf][3] + bz1);
        }
    }
}

/* ------------------------------------------------------------------ */
/* Fused raw logits + row sum-of-squares, float4-vectorized.           */
/* ------------------------------------------------------------------ */
__global__ void __launch_bounds__(256)
attn_kernel(const float* __restrict__ qp, const float* __restrict__ kp)
{
    const int bh   = blockIdx.x;
    const int ch   = blockIdx.y;
    const int warp = threadIdx.x >> 5;
    const int lane = threadIdx.x & 31;
    const int b  = bh / HEADS;
    const int hh = bh % HEADS;

    const float* Q = qp + (size_t)(b*CDIM + hh*CH) * HW;
    const float* K = kp + (size_t)(b*CDIM + hh*CH) * HW;
    const int c0 = warp * 4;

    float acc[4][32];
    #pragma unroll
    for (int i = 0; i < 4; i++)
        #pragma unroll
        for (int d = 0; d < 32; d++) acc[i][d] = 0.f;
    float qs[4] = {0.f,0.f,0.f,0.f};
    float ks[4] = {0.f,0.f,0.f,0.f};

    const int v0 = (ch * ATT_CHUNK) >> 2;
    for (int n = v0 + lane; n < v0 + (ATT_CHUNK >> 2); n += 32) {
        float4 qv[4];
        #pragma unroll
        for (int i = 0; i < 4; i++) {
            qv[i] = ((const float4*)(Q + (size_t)(c0 + i) * HW))[n];
            qs[i] += qv[i].x*qv[i].x + qv[i].y*qv[i].y
                   + qv[i].z*qv[i].z + qv[i].w*qv[i].w;
        }
        #pragma unroll
        for (int i = 0; i < 4; i++) {
            float4 kc = ((const float4*)(K + (size_t)(c0 + i) * HW))[n];
            ks[i] += kc.x*kc.x + kc.y*kc.y + kc.z*kc.z + kc.w*kc.w;
        }
        #pragma unroll
        for (int d = 0; d < 32; d++) {
            float4 kv = ((const float4*)(K + (size_t)d * HW))[n];
            #pragma unroll
            for (int i = 0; i < 4; i++)
                acc[i][d] += qv[i].x*kv.x + qv[i].y*kv.y
                           + qv[i].z*kv.z + qv[i].w*kv.w;
        }
    }

    #pragma unroll
    for (int i = 0; i < 4; i++) {
        float out = 0.f;
        #pragma unroll
        for (int d = 0; d < 32; d++) {
            float v = acc[i][d];
            v += __shfl_xor_sync(0xffffffffu, v, 16);
            v += __shfl_xor_sync(0xffffffffu, v, 8);
            v += __shfl_xor_sync(0xffffffffu, v, 4);
            v += __shfl_xor_sync(0xffffffffu, v, 2);
            v += __shfl_xor_sync(0xffffffffu, v, 1);
            if (lane == d) out = v;
        }
        atomicAdd(&g_attn[bh*CH*CH + (c0 + i)*CH + lane], out);
    }

    #pragma unroll
    for (int i = 0; i < 4; i++) {
        float vq = qs[i], vk = ks[i];
        vq += __shfl_xor_sync(0xffffffffu, vq, 16);
        vq += __shfl_xor_sync(0xffffffffu, vq, 8);
        vq += __shfl_xor_sync(0xffffffffu, vq, 4);
        vq += __shfl_xor_sync(0xffffffffu, vq, 2);
        vq += __shfl_xor_sync(0xffffffffu, vq, 1);
        vk += __shfl_xor_sync(0xffffffffu, vk, 16);
        vk += __shfl_xor_sync(0xffffffffu, vk, 8);
        vk += __shfl_xor_sync(0xffffffffu, vk, 4);
        vk += __shfl_xor_sync(0xffffffffu, vk, 2);
        vk += __shfl_xor_sync(0xffffffffu, vk, 1);
        if (lane == 0) {
            int row = b*CDIM + hh*CH + c0 + i;
            atomicAdd(&g_ss[row], vq);
            atomicAdd(&g_ss[NROWS + row], vk);
        }
    }
}

/* ------------------------------------------------------------------ */
__global__ void softmax_kernel(const float* __restrict__ temp)
{
    const int bh = blockIdx.x;
    const int b  = bh / HEADS;
    const int hh = bh % HEADS;
    const int c  = threadIdx.y;
    const int d  = threadIdx.x;

    const int rowq = b*CDIM + hh*CH + c;
    const int rowk = b*CDIM + hh*CH + d;
    float rq = 1.f / fmaxf(sqrtf(g_ss[rowq]), 1e-12f);
    float rk = 1.f / fmaxf(sqrtf(g_ss[NROWS + rowk]), 1e-12f);

    int idx = bh*CH*CH + c*CH + d;
    float v = g_attn[idx] * rq * rk * temp[hh];

    float m = v;
    m = fmaxf(m, __shfl_xor_sync(0xffffffffu, m, 16));
    m = fmaxf(m, __shfl_xor_sync(0xffffffffu, m, 8));
    m = fmaxf(m, __shfl_xor_sync(0xffffffffu, m, 4));
    m = fmaxf(m, __shfl_xor_sync(0xffffffffu, m, 2));
    m = fmaxf(m, __shfl_xor_sync(0xffffffffu, m, 1));
    float e = __expf(v - m);
    float s = e;
    s += __shfl_xor_sync(0xffffffffu, s, 16);
    s += __shfl_xor_sync(0xffffffffu, s, 8);
    s += __shfl_xor_sync(0xffffffffu, s, 4);
    s += __shfl_xor_sync(0xffffffffu, s, 2);
    s += __shfl_xor_sync(0xffffffffu, s, 1);
    g_attn[idx] = e / s;
}

/* ------------------------------------------------------------------ */
__global__ void weff_kernel(const float* __restrict__ wo)
{
    const int b   = blockIdx.y;
    const int idx = blockIdx.x * 256 + threadIdx.x;
    const int o   = idx / CDIM;
    const int dg  = idx % CDIM;
    const int h   = dg / CH;
    const int dc  = dg % CH;

    const float* P    = g_attn + ((b*HEADS + h)*CH)*CH;
    const float* wrow = wo + o*CDIM + h*CH;
    float s = 0.f;
    #pragma unroll
    for (int c = 0; c < CH; c++)
        s += wrow[c] * P[c*CH + dc];

    size_t off = (size_t)b*WSZ + o*CDIM + dg;
    __nv_bfloat16 hw = __float2bfloat16(s);
    g_weffh[off] = hw;
    g_weffl[off] = __float2bfloat16(s - __bfloat162float(hw));
}

/* ------------------------------------------------------------------ */
extern "C" void kernel_launch(void* const* d_in, const int* in_sizes, int n_in,
                              void* d_out, int out_size)
{
    const float* q    = (const float*)d_in[0];
    const float* k    = (const float*)d_in[1];
    const float* v    = (const float*)d_in[2];
    const float* wq   = (const float*)d_in[3];
    const float* bq   = (const float*)d_in[4];
    const float* wk   = (const float*)d_in[5];
    const float* bk   = (const float*)d_in[6];
    const float* wv   = (const float*)d_in[7];
    const float* bv   = (const float*)d_in[8];
    const float* wo   = (const float*)d_in[9];
    const float* bo   = (const float*)d_in[10];
    const float* temp = (const float*)d_in[11];

    float *qp, *kp, *vp;
    __nv_bfloat16 *wh, *wl, *weh, *wel;
    cudaGetSymbolAddress((void**)&qp,  g_qp);
    cudaGetSymbolAddress((void**)&kp,  g_kp);
    cudaGetSymbolAddress((void**)&vp,  g_vp);
    cudaGetSymbolAddress((void**)&wh,  g_wh);
    cudaGetSymbolAddress((void**)&wl,  g_wl);
    cudaGetSymbolAddress((void**)&weh, g_weffh);
    cudaGetSymbolAddress((void**)&wel, g_weffl);

    const int smem_bytes = S_WORDS * 4;
    cudaFuncSetAttribute(gemm_bf16, cudaFuncAttributeMaxDynamicSharedMemorySize,
                         smem_bytes);

    zero_kernel<<<(NBH*CH*CH + 255)/256, 256>>>();
    prep_w<<<(3*WSZ + 255)/256, 256>>>(wq, wk, wv);

    dim3 gg(HW/128, CDIM/64, BATCH);
    gemm_bf16<<<gg, 256, smem_bytes>>>(q, wh + 0*WSZ, wl + 0*WSZ, bq, qp, 0);
    gemm_bf16<<<gg, 256, smem_bytes>>>(k, wh + 1*WSZ, wl + 1*WSZ, bk, kp, 0);
    gemm_bf16<<<gg, 256, smem_bytes>>>(v, wh + 2*WSZ, wl + 2*WSZ, bv, vp, 0);

    attn_kernel<<<dim3(NBH, ATT_CHUNKS), 256>>>(qp, kp);
    softmax_kernel<<<NBH, dim3(32, 32)>>>(temp);
    weff_kernel<<<dim3((CDIM*CDIM)/256, BATCH), 256>>>(wo);

    gemm_bf16<<<gg, 256, smem_bytes>>>(vp, weh, wel, bo, (float*)d_out, WSZ);
}

// round 13
// speedup vs baseline: 3.7916x; 1.0416x over previous
#include <cuda_runtime.h>
#include <cuda_bf16.h>
#include <cstdint>

#define HW    16384
#define BATCH 8
#define CDIM  192
#define HEADS 6
#define CH    32
#define NROWS (BATCH*CDIM)      /* 1536 */
#define NBH   (BATCH*HEADS)     /* 48   */
#define ATT_CHUNKS 8
#define ATT_CHUNK  (HW/ATT_CHUNKS)
#define WSZ   (CDIM*CDIM)       /* 36864 */

/* ------------------------------------------------------------------ */
/* Scratch (device globals: no allocations allowed)                    */
/* ------------------------------------------------------------------ */
__device__ float g_qp[BATCH*CDIM*HW];
__device__ float g_kp[BATCH*CDIM*HW];
__device__ float g_vp[BATCH*CDIM*HW];
__device__ float g_attn[NBH*CH*CH];
__device__ float g_ss[2*NROWS];
__device__ __nv_bfloat16 g_wh[3*WSZ];
__device__ __nv_bfloat16 g_wl[3*WSZ];
__device__ __nv_bfloat16 g_weffh[BATCH*WSZ];
__device__ __nv_bfloat16 g_weffl[BATCH*WSZ];

/* ------------------------------------------------------------------ */
__global__ void zero_kernel() {
    int i = blockIdx.x * 256 + threadIdx.x;
    if (i < NBH*CH*CH) g_attn[i] = 0.f;
    if (i < 2*NROWS)   g_ss[i]   = 0.f;
}

__global__ void prep_w(const float* __restrict__ wq,
                       const float* __restrict__ wk,
                       const float* __restrict__ wv)
{
    int i = blockIdx.x * 256 + threadIdx.x;
    if (i >= 3*WSZ) return;
    const float* src = (i < WSZ) ? wq : (i < 2*WSZ ? wk : wv);
    float x = src[i % WSZ];
    __nv_bfloat16 h = __float2bfloat16(x);
    g_wh[i] = h;
    g_wl[i] = __float2bfloat16(x - __bfloat162float(h));
}

/* ------------------------------------------------------------------ */
/* bf16-split tensor-core conv1x1, ldmatrix + mma.sync.m16n8k16.
 * CTA: FULL 192(M=cout) x 128(N=spatial), 512 threads, 16 warps as
 * 4(M) x 4(N) -> warp tile 48x32. K=192 in 3 chunks of 64.
 * X converted ONCE per tile (was 3x across m-block CTAs).
 * Raw fp32 X for chunk c+1 cp.async'd into the stage during MMA.     */
/* ------------------------------------------------------------------ */
/* SMEM word map */
#define ASTR  36
#define BSTR  36
#define SA_HI 0
#define SA_LO (192*ASTR)                 /* 6912  */
#define SB_HI (2*192*ASTR)               /* 13824 */
#define SB_LO (2*192*ASTR + 128*BSTR)    /* 18432 */
#define STG   (2*192*ASTR + 2*128*BSTR)  /* 23040 */
#define S_WORDS (STG + 64*128)           /* 31232 words = 124928 B */

__device__ __forceinline__ uint32_t smem_u32(const void* p) {
    uint32_t a;
    asm("{ .reg .u64 t; cvta.to.shared.u64 t, %1; cvt.u32.u64 %0, t; }"
        : "=r"(a) : "l"(p));
    return a;
}
__device__ __forceinline__ void cp16(uint32_t saddr, const void* g) {
    asm volatile("cp.async.cg.shared.global [%0], [%1], 16;"
                 :: "r"(saddr), "l"(g));
}
#define CP_COMMIT() asm volatile("cp.async.commit_group;" ::: "memory")
#define CP_WAIT0()  asm volatile("cp.async.wait_group 0;" ::: "memory")

__device__ __forceinline__ void ldm_x4(uint32_t* r, uint32_t addr) {
    asm volatile("ldmatrix.sync.aligned.m8n8.x4.shared.b16 {%0,%1,%2,%3}, [%4];"
        : "=r"(r[0]), "=r"(r[1]), "=r"(r[2]), "=r"(r[3]) : "r"(addr));
}
__device__ __forceinline__ void mma_bf16(float* c, const uint32_t* a, const uint32_t* b) {
    asm volatile(
        "mma.sync.aligned.m16n8k16.row.col.f32.bf16.bf16.f32 "
        "{%0,%1,%2,%3}, {%4,%5,%6,%7}, {%8,%9}, {%0,%1,%2,%3};"
        : "+f"(c[0]), "+f"(c[1]), "+f"(c[2]), "+f"(c[3])
        : "r"(a[0]), "r"(a[1]), "r"(a[2]), "r"(a[3]), "r"(b[0]), "r"(b[1]));
}

__global__ void __launch_bounds__(512, 1)
gemm_bf16(const float* __restrict__ X,
          const __nv_bfloat16* __restrict__ Whi,
          const __nv_bfloat16* __restrict__ Wlo,
          const float* __restrict__ bias,
          float* __restrict__ Y, int wstride)
{
    extern __shared__ uint32_t sm[];
    const uint32_t sbase = smem_u32(sm);

    const int tid  = threadIdx.x;
    const int wid  = tid >> 5;       /* 0..15 */
    const int lane = tid & 31;
    const int grp  = lane >> 2;
    const int tig  = lane & 3;
    const int wm   = wid & 3;        /* m quarter: 48 rows  */
    const int wn   = wid >> 2;       /* n quarter: 32 cols  */

    const int n0 = blockIdx.x * 128;
    const int b  = blockIdx.y;

    const float* Xb = X + (size_t)b * CDIM * HW;
    float*       Yb = Y + (size_t)b * CDIM * HW;
    const __nv_bfloat16* Wh = Whi + (size_t)b * wstride;
    const __nv_bfloat16* Wl = Wlo + (size_t)b * wstride;

    /* ldmatrix addressing */
    const int a_row  = lane & 15;
    const int a_koff = (lane >> 4) * 4;
    const int b_row  = (lane & 7) + ((lane >> 4) << 3);
    const int b_koff = ((lane >> 3) & 1) * 4;

    float acc[3][4][4];
    #pragma unroll
    for (int i = 0; i < 3; i++)
        #pragma unroll
        for (int j = 0; j < 4; j++)
            #pragma unroll
            for (int r = 0; r < 4; r++) acc[i][j][r] = 0.f;

    /* prologue: stage <- chunk 0 raw fp32 (64 k x 128 n) */
    #pragma unroll
    for (int r = 0; r < 4; r++) {
        int u = tid + 512*r;
        int k = u >> 5, seg = u & 31;
        cp16(sbase + (STG + k*128 + seg*4)*4,
             Xb + (size_t)k * HW + n0 + seg*4);
    }
    CP_COMMIT();

    for (int c = 0; c < 3; c++) {
        const int k0 = c * 64;
        CP_WAIT0();
        __syncthreads();     /* stage[c] ready; operand buffers free */

        /* A: full-M chunk weights hi/lo -> SMEM (uint4) : 1536 rows*kg */
        #pragma unroll
        for (int r = 0; r < 3; r++) {
            int i = tid + 512*r;
            int m = i >> 3, kg = i & 7;
            *(uint4*)&sm[SA_HI + m*ASTR + kg*4] =
                *(const uint4*)&Wh[m*CDIM + k0 + 8*kg];
            *(uint4*)&sm[SA_LO + m*ASTR + kg*4] =
                *(const uint4*)&Wl[m*CDIM + k0 + 8*kg];
        }

        /* convert stage (fp32) -> B operand (bf16 hi/lo): 1024 (nn,kg) */
        #pragma unroll
        for (int it2 = 0; it2 < 2; it2++) {
            int id = tid + 512*it2;
            int nn = id & 127;
            int kg = id >> 7;
            uint32_t hi[4], lo[4];
            #pragma unroll
            for (int j = 0; j < 4; j++) {
                float x0 = __uint_as_float(sm[STG + (8*kg + 2*j)*128 + nn]);
                float x1 = __uint_as_float(sm[STG + (8*kg + 2*j+1)*128 + nn]);
                __nv_bfloat16 h0 = __float2bfloat16(x0);
                __nv_bfloat16 h1 = __float2bfloat16(x1);
                __nv_bfloat16 l0 = __float2bfloat16(x0 - __bfloat162float(h0));
                __nv_bfloat16 l1 = __float2bfloat16(x1 - __bfloat162float(h1));
                hi[j] = (uint32_t)__bfloat16_as_ushort(h0)
                      | ((uint32_t)__bfloat16_as_ushort(h1) << 16);
                lo[j] = (uint32_t)__bfloat16_as_ushort(l0)
                      | ((uint32_t)__bfloat16_as_ushort(l1) << 16);
            }
            *(uint4*)&sm[SB_HI + nn*BSTR + kg*4] = make_uint4(hi[0],hi[1],hi[2],hi[3]);
            *(uint4*)&sm[SB_LO + nn*BSTR + kg*4] = make_uint4(lo[0],lo[1],lo[2],lo[3]);
        }
        __syncthreads();     /* operands ready; stage fully consumed */

        /* prefetch next chunk into the (now free) stage during MMA */
        if (c < 2) {
            const int nk0 = k0 + 64;
            #pragma unroll
            for (int r = 0; r < 4; r++) {
                int u = tid + 512*r;
                int k = u >> 5, seg = u & 31;
                cp16(sbase + (STG + k*128 + seg*4)*4,
                     Xb + (size_t)(nk0 + k) * HW + n0 + seg*4);
            }
        }
        CP_COMMIT();

        /* MMA over chunk c : 3 m-frags x 4 n-frags x 3 splits */
        #pragma unroll
        for (int s = 0; s < 4; s++) {
            uint32_t ah[3][4], al[3][4], bh[2][4], bl[2][4];
            #pragma unroll
            for (int mf = 0; mf < 3; mf++) {
                uint32_t off = ((wm*48 + mf*16 + a_row)*ASTR + s*8 + a_koff) * 4;
                ldm_x4(ah[mf], sbase + SA_HI*4 + off);
                ldm_x4(al[mf], sbase + SA_LO*4 + off);
            }
            #pragma unroll
            for (int np = 0; np < 2; np++) {
                uint32_t off = ((wn*32 + np*16 + b_row)*BSTR + s*8 + b_koff) * 4;
                ldm_x4(bh[np], sbase + SB_HI*4 + off);
                ldm_x4(bl[np], sbase + SB_LO*4 + off);
            }
            #pragma unroll
            for (int mf = 0; mf < 3; mf++)
                #pragma unroll
                for (int nf = 0; nf < 4; nf++) {
                    const uint32_t* pbh = &bh[nf>>1][(nf&1)*2];
                    const uint32_t* pbl = &bl[nf>>1][(nf&1)*2];
                    mma_bf16(acc[mf][nf], ah[mf], pbh);
                    mma_bf16(acc[mf][nf], ah[mf], pbl);
                    mma_bf16(acc[mf][nf], al[mf], pbh);
                }
        }
        __syncthreads();     /* done with operand buffers before restage */
    }

    /* epilogue */
    #pragma unroll
    for (int mf = 0; mf < 3; mf++) {
        int mr = wm*48 + mf*16 + grp;
        float bz0 = __ldg(&bias[mr]);
        float bz1 = __ldg(&bias[mr + 8]);
        #pragma unroll
        for (int nf = 0; nf < 4; nf++) {
            int n = n0 + wn*32 + nf*8 + tig*2;
            *(float2*)&Yb[(size_t)mr * HW + n] =
                make_float2(acc[mf][nf][0] + bz0, acc[mf][nf][1] + bz0);
            *(float2*)&Yb[(size_t)(mr + 8) * HW + n] =
                make_float2(acc[mf][nf][2] + bz1, acc[mf][nf][3] + bz1);
        }
    }
}

/* ------------------------------------------------------------------ */
/* Fused raw logits + row sum-of-squares, float4-vectorized.           */
/* ------------------------------------------------------------------ */
__global__ void __launch_bounds__(256)
attn_kernel(const float* __restrict__ qp, const float* __restrict__ kp)
{
    const int bh   = blockIdx.x;
    const int ch   = blockIdx.y;
    const int warp = threadIdx.x >> 5;
    const int lane = threadIdx.x & 31;
    const int b  = bh / HEADS;
    const int hh = bh % HEADS;

    const float* Q = qp + (size_t)(b*CDIM + hh*CH) * HW;
    const float* K = kp + (size_t)(b*CDIM + hh*CH) * HW;
    const int c0 = warp * 4;

    float acc[4][32];
    #pragma unroll
    for (int i = 0; i < 4; i++)
        #pragma unroll
        for (int d = 0; d < 32; d++) acc[i][d] = 0.f;
    float qs[4] = {0.f,0.f,0.f,0.f};
    float ks[4] = {0.f,0.f,0.f,0.f};

    const int v0 = (ch * ATT_CHUNK) >> 2;
    for (int n = v0 + lane; n < v0 + (ATT_CHUNK >> 2); n += 32) {
        float4 qv[4];
        #pragma unroll
        for (int i = 0; i < 4; i++) {
            qv[i] = ((const float4*)(Q + (size_t)(c0 + i) * HW))[n];
            qs[i] += qv[i].x*qv[i].x + qv[i].y*qv[i].y
                   + qv[i].z*qv[i].z + qv[i].w*qv[i].w;
        }
        #pragma unroll
        for (int i = 0; i < 4; i++) {
            float4 kc = ((const float4*)(K + (size_t)(c0 + i) * HW))[n];
            ks[i] += kc.x*kc.x + kc.y*kc.y + kc.z*kc.z + kc.w*kc.w;
        }
        #pragma unroll
        for (int d = 0; d < 32; d++) {
            float4 kv = ((const float4*)(K + (size_t)d * HW))[n];
            #pragma unroll
            for (int i = 0; i < 4; i++)
                acc[i][d] += qv[i].x*kv.x + qv[i].y*kv.y
                           + qv[i].z*kv.z + qv[i].w*kv.w;
        }
    }

    #pragma unroll
    for (int i = 0; i < 4; i++) {
        float out = 0.f;
        #pragma unroll
        for (int d = 0; d < 32; d++) {
            float v = acc[i][d];
            v += __shfl_xor_sync(0xffffffffu, v, 16);
            v += __shfl_xor_sync(0xffffffffu, v, 8);
            v += __shfl_xor_sync(0xffffffffu, v, 4);
            v += __shfl_xor_sync(0xffffffffu, v, 2);
            v += __shfl_xor_sync(0xffffffffu, v, 1);
            if (lane == d) out = v;
        }
        atomicAdd(&g_attn[bh*CH*CH + (c0 + i)*CH + lane], out);
    }

    #pragma unroll
    for (int i = 0; i < 4; i++) {
        float vq = qs[i], vk = ks[i];
        vq += __shfl_xor_sync(0xffffffffu, vq, 16);
        vq += __shfl_xor_sync(0xffffffffu, vq, 8);
        vq += __shfl_xor_sync(0xffffffffu, vq, 4);
        vq += __shfl_xor_sync(0xffffffffu, vq, 2);
        vq += __shfl_xor_sync(0xffffffffu, vq, 1);
        vk += __shfl_xor_sync(0xffffffffu, vk, 16);
        vk += __shfl_xor_sync(0xffffffffu, vk, 8);
        vk += __shfl_xor_sync(0xffffffffu, vk, 4);
        vk += __shfl_xor_sync(0xffffffffu, vk, 2);
        vk += __shfl_xor_sync(0xffffffffu, vk, 1);
        if (lane == 0) {
            int row = b*CDIM + hh*CH + c0 + i;
            atomicAdd(&g_ss[row], vq);
            atomicAdd(&g_ss[NROWS + row], vk);
        }
    }
}

/* ------------------------------------------------------------------ */
__global__ void softmax_kernel(const float* __restrict__ temp)
{
    const int bh = blockIdx.x;
    const int b  = bh / HEADS;
    const int hh = bh % HEADS;
    const int c  = threadIdx.y;
    const int d  = threadIdx.x;

    const int rowq = b*CDIM + hh*CH + c;
    const int rowk = b*CDIM + hh*CH + d;
    float rq = 1.f / fmaxf(sqrtf(g_ss[rowq]), 1e-12f);
    float rk = 1.f / fmaxf(sqrtf(g_ss[NROWS + rowk]), 1e-12f);

    int idx = bh*CH*CH + c*CH + d;
    float v = g_attn[idx] * rq * rk * temp[hh];

    float m = v;
    m = fmaxf(m, __shfl_xor_sync(0xffffffffu, m, 16));
    m = fmaxf(m, __shfl_xor_sync(0xffffffffu, m, 8));
    m = fmaxf(m, __shfl_xor_sync(0xffffffffu, m, 4));
    m = fmaxf(m, __shfl_xor_sync(0xffffffffu, m, 2));
    m = fmaxf(m, __shfl_xor_sync(0xffffffffu, m, 1));
    float e = __expf(v - m);
    float s = e;
    s += __shfl_xor_sync(0xffffffffu, s, 16);
    s += __shfl_xor_sync(0xffffffffu, s, 8);
    s += __shfl_xor_sync(0xffffffffu, s, 4);
    s += __shfl_xor_sync(0xffffffffu, s, 2);
    s += __shfl_xor_sync(0xffffffffu, s, 1);
    g_attn[idx] = e / s;
}

/* ------------------------------------------------------------------ */
__global__ void weff_kernel(const float* __restrict__ wo)
{
    const int b   = blockIdx.y;
    const int idx = blockIdx.x * 256 + threadIdx.x;
    const int o   = idx / CDIM;
    const int dg  = idx % CDIM;
    const int h   = dg / CH;
    const int dc  = dg % CH;

    const float* P    = g_attn + ((b*HEADS + h)*CH)*CH;
    const float* wrow = wo + o*CDIM + h*CH;
    float s = 0.f;
    #pragma unroll
    for (int c = 0; c < CH; c++)
        s += wrow[c] * P[c*CH + dc];

    size_t off = (size_t)b*WSZ + o*CDIM + dg;
    __nv_bfloat16 hw = __float2bfloat16(s);
    g_weffh[off] = hw;
    g_weffl[off] = __float2bfloat16(s - __bfloat162float(hw));
}

/* ------------------------------------------------------------------ */
extern "C" void kernel_launch(void* const* d_in, const int* in_sizes, int n_in,
                              void* d_out, int out_size)
{
    const float* q    = (const float*)d_in[0];
    const float* k    = (const float*)d_in[1];
    const float* v    = (const float*)d_in[2];
    const float* wq   = (const float*)d_in[3];
    const float* bq   = (const float*)d_in[4];
    const float* wk   = (const float*)d_in[5];
    const float* bk   = (const float*)d_in[6];
    const float* wv   = (const float*)d_in[7];
    const float* bv   = (const float*)d_in[8];
    const float* wo   = (const float*)d_in[9];
    const float* bo   = (const float*)d_in[10];
    const float* temp = (const float*)d_in[11];

    float *qp, *kp, *vp;
    __nv_bfloat16 *wh, *wl, *weh, *wel;
    cudaGetSymbolAddress((void**)&qp,  g_qp);
    cudaGetSymbolAddress((void**)&kp,  g_kp);
    cudaGetSymbolAddress((void**)&vp,  g_vp);
    cudaGetSymbolAddress((void**)&wh,  g_wh);
    cudaGetSymbolAddress((void**)&wl,  g_wl);
    cudaGetSymbolAddress((void**)&weh, g_weffh);
    cudaGetSymbolAddress((void**)&wel, g_weffl);

    const int smem_bytes = S_WORDS * 4;
    cudaFuncSetAttribute(gemm_bf16, cudaFuncAttributeMaxDynamicSharedMemorySize,
                         smem_bytes);

    zero_kernel<<<(NBH*CH*CH + 255)/256, 256>>>();
    prep_w<<<(3*WSZ + 255)/256, 256>>>(wq, wk, wv);

    dim3 gg(HW/128, BATCH);
    gemm_bf16<<<gg, 512, smem_bytes>>>(q, wh + 0*WSZ, wl + 0*WSZ, bq, qp, 0);
    gemm_bf16<<<gg, 512, smem_bytes>>>(k, wh + 1*WSZ, wl + 1*WSZ, bk, kp, 0);
    gemm_bf16<<<gg, 512, smem_bytes>>>(v, wh + 2*WSZ, wl + 2*WSZ, bv, vp, 0);

    attn_kernel<<<dim3(NBH, ATT_CHUNKS), 256>>>(qp, kp);
    softmax_kernel<<<NBH, dim3(32, 32)>>>(temp);
    weff_kernel<<<dim3((CDIM*CDIM)/256, BATCH), 256>>>(wo);

    gemm_bf16<<<gg, 512, smem_bytes>>>(vp, weh, wel, bo, (float*)d_out, WSZ);
}

// round 14
// speedup vs baseline: 3.9496x; 1.0417x over previous
#include <cuda_runtime.h>
#include <cuda_bf16.h>
#include <cstdint>

#define HW    16384
#define BATCH 8
#define CDIM  192
#define HEADS 6
#define CH    32
#define NROWS (BATCH*CDIM)      /* 1536 */
#define NBH   (BATCH*HEADS)     /* 48   */
#define ATT_CHUNKS 8
#define ATT_CHUNK  (HW/ATT_CHUNKS)
#define WSZ   (CDIM*CDIM)       /* 36864 */

/* ------------------------------------------------------------------ */
/* Scratch (device globals: no allocations allowed)                    */
/* ------------------------------------------------------------------ */
__device__ float g_qp[BATCH*CDIM*HW];
__device__ float g_kp[BATCH*CDIM*HW];
__device__ float g_vp[BATCH*CDIM*HW];
__device__ float g_attn[NBH*CH*CH];
__device__ float g_ss[2*NROWS];
__device__ __nv_bfloat16 g_wh[3*WSZ];
__device__ __nv_bfloat16 g_wl[3*WSZ];
__device__ __nv_bfloat16 g_weffh[BATCH*WSZ];
__device__ __nv_bfloat16 g_weffl[BATCH*WSZ];

/* ------------------------------------------------------------------ */
__global__ void zero_kernel() {
    int i = blockIdx.x * 256 + threadIdx.x;
    if (i < NBH*CH*CH) g_attn[i] = 0.f;
    if (i < 2*NROWS)   g_ss[i]   = 0.f;
}

__global__ void prep_w(const float* __restrict__ wq,
                       const float* __restrict__ wk,
                       const float* __restrict__ wv)
{
    int i = blockIdx.x * 256 + threadIdx.x;
    if (i >= 3*WSZ) return;
    const float* src = (i < WSZ) ? wq : (i < 2*WSZ ? wk : wv);
    float x = src[i % WSZ];
    __nv_bfloat16 h = __float2bfloat16(x);
    g_wh[i] = h;
    g_wl[i] = __float2bfloat16(x - __bfloat162float(h));
}

/* ------------------------------------------------------------------ */
/* bf16-split tensor-core conv1x1, ldmatrix + mma.sync.m16n8k16.
 * CTA: FULL 192(M) x 128(N), 512 threads, 16 warps = 4(M) x 4(N),
 * warp tile 48x32. K=192 in 3 chunks of 64.
 * DOUBLE-BUFFERED operands + ONE barrier per chunk:
 *   iter c: { stage A/B for chunk c+1 into buf[nxt] ;
 *             MMA chunk c from buf[cur] ; __syncthreads }
 * -> convert/load of c+1 overlaps MMA of c via in-warp ILP and
 *    cross-warp drift (no phase barrier between them).               */
/* ------------------------------------------------------------------ */
/* SMEM word map */
#define ASTR  36
#define BSTR  36
#define A_BUF (192*ASTR)              /* 6912 words per A half (hi or lo) */
#define B_BUF (128*BSTR)              /* 4608 words per B half */
#define SA_OFF(buf) ((buf)*2*A_BUF)              /* hi; lo at +A_BUF */
#define SB_OFF(buf) (4*A_BUF + (buf)*2*B_BUF)    /* hi; lo at +B_BUF */
#define S_WORDS (4*A_BUF + 4*B_BUF)   /* 46080 words = 184320 B */

__device__ __forceinline__ uint32_t smem_u32(const void* p) {
    uint32_t a;
    asm("{ .reg .u64 t; cvta.to.shared.u64 t, %1; cvt.u32.u64 %0, t; }"
        : "=r"(a) : "l"(p));
    return a;
}
__device__ __forceinline__ void ldm_x4(uint32_t* r, uint32_t addr) {
    asm volatile("ldmatrix.sync.aligned.m8n8.x4.shared.b16 {%0,%1,%2,%3}, [%4];"
        : "=r"(r[0]), "=r"(r[1]), "=r"(r[2]), "=r"(r[3]) : "r"(addr));
}
__device__ __forceinline__ void mma_bf16(float* c, const uint32_t* a, const uint32_t* b) {
    asm volatile(
        "mma.sync.aligned.m16n8k16.row.col.f32.bf16.bf16.f32 "
        "{%0,%1,%2,%3}, {%4,%5,%6,%7}, {%8,%9}, {%0,%1,%2,%3};"
        : "+f"(c[0]), "+f"(c[1]), "+f"(c[2]), "+f"(c[3])
        : "r"(a[0]), "r"(a[1]), "r"(a[2]), "r"(a[3]), "r"(b[0]), "r"(b[1]));
}

__global__ void __launch_bounds__(512, 1)
gemm_bf16(const float* __restrict__ X,
          const __nv_bfloat16* __restrict__ Whi,
          const __nv_bfloat16* __restrict__ Wlo,
          const float* __restrict__ bias,
          float* __restrict__ Y, int wstride)
{
    extern __shared__ uint32_t sm[];
    const uint32_t sbase = smem_u32(sm);

    const int tid  = threadIdx.x;
    const int wid  = tid >> 5;       /* 0..15 */
    const int lane = tid & 31;
    const int grp  = lane >> 2;
    const int tig  = lane & 3;
    const int wm   = wid & 3;        /* m quarter: 48 rows  */
    const int wn   = wid >> 2;       /* n quarter: 32 cols  */

    const int n0 = blockIdx.x * 128;
    const int b  = blockIdx.y;

    const float* Xb = X + (size_t)b * CDIM * HW;
    float*       Yb = Y + (size_t)b * CDIM * HW;
    const __nv_bfloat16* Wh = Whi + (size_t)b * wstride;
    const __nv_bfloat16* Wl = Wlo + (size_t)b * wstride;

    /* staging work partitions (fixed per thread) */
    const int am  = tid >> 3;        /* A rows handled: am, am+64, am+128 */
    const int akg = tid & 7;
    const int bnn = tid & 127;       /* B: (nn, kg) and (nn, kg+4) */
    const int bkg = tid >> 7;        /* 0..3 */

    /* ldmatrix addressing */
    const int a_row  = lane & 15;
    const int a_koff = (lane >> 4) * 4;
    const int b_row  = (lane & 7) + ((lane >> 4) << 3);
    const int b_koff = ((lane >> 3) & 1) * 4;

    float acc[3][4][4];
    #pragma unroll
    for (int i = 0; i < 3; i++)
        #pragma unroll
        for (int j = 0; j < 4; j++)
            #pragma unroll
            for (int r = 0; r < 4; r++) acc[i][j][r] = 0.f;

    /* ---- staging helpers (inlined via lambdas) ---- */
    auto stage_chunk = [&](int k0, int buf) {
        /* A: 192 rows x 8 kgroups, hi/lo (uint4 = 8 bf16) */
        #pragma unroll
        for (int r = 0; r < 3; r++) {
            int m = am + r*64;
            *(uint4*)&sm[SA_OFF(buf) + m*ASTR + akg*4] =
                *(const uint4*)&Wh[m*CDIM + k0 + 8*akg];
            *(uint4*)&sm[SA_OFF(buf) + A_BUF + m*ASTR + akg*4] =
                *(const uint4*)&Wl[m*CDIM + k0 + 8*akg];
        }
        /* B: convert fp32 X -> bf16 hi/lo, transposed [nn][kpair] */
        #pragma unroll
        for (int it2 = 0; it2 < 2; it2++) {
            int kg = bkg + it2*4;
            const float* xp = Xb + (size_t)(k0 + 8*kg) * HW + n0 + bnn;
            uint32_t hi[4], lo[4];
            #pragma unroll
            for (int j = 0; j < 4; j++) {
                float x0 = xp[(size_t)(2*j)   * HW];
                float x1 = xp[(size_t)(2*j+1) * HW];
                __nv_bfloat16 h0 = __float2bfloat16(x0);
                __nv_bfloat16 h1 = __float2bfloat16(x1);
                __nv_bfloat16 l0 = __float2bfloat16(x0 - __bfloat162float(h0));
                __nv_bfloat16 l1 = __float2bfloat16(x1 - __bfloat162float(h1));
                hi[j] = (uint32_t)__bfloat16_as_ushort(h0)
                      | ((uint32_t)__bfloat16_as_ushort(h1) << 16);
                lo[j] = (uint32_t)__bfloat16_as_ushort(l0)
                      | ((uint32_t)__bfloat16_as_ushort(l1) << 16);
            }
            *(uint4*)&sm[SB_OFF(buf) + bnn*BSTR + kg*4] =
                make_uint4(hi[0],hi[1],hi[2],hi[3]);
            *(uint4*)&sm[SB_OFF(buf) + B_BUF + bnn*BSTR + kg*4] =
                make_uint4(lo[0],lo[1],lo[2],lo[3]);
        }
    };

    /* prologue: buf0 <- chunk 0 */
    stage_chunk(0, 0);
    __syncthreads();

    for (int c = 0; c < 3; c++) {
        const int cur = c & 1, nxt = cur ^ 1;

        /* stage chunk c+1 into buf[nxt] (overlaps MMA below) */
        if (c < 2) stage_chunk((c + 1) * 64, nxt);

        /* MMA over chunk c from buf[cur] */
        const uint32_t abase = sbase + SA_OFF(cur)*4;
        const uint32_t bbase = sbase + SB_OFF(cur)*4;
        #pragma unroll
        for (int s = 0; s < 4; s++) {
            uint32_t ah[3][4], al[3][4], bh[2][4], bl[2][4];
            #pragma unroll
            for (int mf = 0; mf < 3; mf++) {
                uint32_t off = ((wm*48 + mf*16 + a_row)*ASTR + s*8 + a_koff) * 4;
                ldm_x4(ah[mf], abase + off);
                ldm_x4(al[mf], abase + A_BUF*4 + off);
            }
            #pragma unroll
            for (int np = 0; np < 2; np++) {
                uint32_t off = ((wn*32 + np*16 + b_row)*BSTR + s*8 + b_koff) * 4;
                ldm_x4(bh[np], bbase + off);
                ldm_x4(bl[np], bbase + B_BUF*4 + off);
            }
            #pragma unroll
            for (int mf = 0; mf < 3; mf++)
                #pragma unroll
                for (int nf = 0; nf < 4; nf++) {
                    const uint32_t* pbh = &bh[nf>>1][(nf&1)*2];
                    const uint32_t* pbl = &bl[nf>>1][(nf&1)*2];
                    mma_bf16(acc[mf][nf], ah[mf], pbh);
                    mma_bf16(acc[mf][nf], ah[mf], pbl);
                    mma_bf16(acc[mf][nf], al[mf], pbh);
                }
        }
        __syncthreads();   /* single barrier per chunk */
    }

    /* epilogue */
    #pragma unroll
    for (int mf = 0; mf < 3; mf++) {
        int mr = wm*48 + mf*16 + grp;
        float bz0 = __ldg(&bias[mr]);
        float bz1 = __ldg(&bias[mr + 8]);
        #pragma unroll
        for (int nf = 0; nf < 4; nf++) {
            int n = n0 + wn*32 + nf*8 + tig*2;
            *(float2*)&Yb[(size_t)mr * HW + n] =
                make_float2(acc[mf][nf][0] + bz0, acc[mf][nf][1] + bz0);
            *(float2*)&Yb[(size_t)(mr + 8) * HW + n] =
                make_float2(acc[mf][nf][2] + bz1, acc[mf][nf][3] + bz1);
        }
    }
}

/* ------------------------------------------------------------------ */
/* Fused raw logits + row sum-of-squares, float4-vectorized.           */
/* ------------------------------------------------------------------ */
__global__ void __launch_bounds__(256)
attn_kernel(const float* __restrict__ qp, const float* __restrict__ kp)
{
    const int bh   = blockIdx.x;
    const int ch   = blockIdx.y;
    const int warp = threadIdx.x >> 5;
    const int lane = threadIdx.x & 31;
    const int b  = bh / HEADS;
    const int hh = bh % HEADS;

    const float* Q = qp + (size_t)(b*CDIM + hh*CH) * HW;
    const float* K = kp + (size_t)(b*CDIM + hh*CH) * HW;
    const int c0 = warp * 4;

    float acc[4][32];
    #pragma unroll
    for (int i = 0; i < 4; i++)
        #pragma unroll
        for (int d = 0; d < 32; d++) acc[i][d] = 0.f;
    float qs[4] = {0.f,0.f,0.f,0.f};
    float ks[4] = {0.f,0.f,0.f,0.f};

    const int v0 = (ch * ATT_CHUNK) >> 2;
    for (int n = v0 + lane; n < v0 + (ATT_CHUNK >> 2); n += 32) {
        float4 qv[4];
        #pragma unroll
        for (int i = 0; i < 4; i++) {
            qv[i] = ((const float4*)(Q + (size_t)(c0 + i) * HW))[n];
            qs[i] += qv[i].x*qv[i].x + qv[i].y*qv[i].y
                   + qv[i].z*qv[i].z + qv[i].w*qv[i].w;
        }
        #pragma unroll
        for (int i = 0; i < 4; i++) {
            float4 kc = ((const float4*)(K + (size_t)(c0 + i) * HW))[n];
            ks[i] += kc.x*kc.x + kc.y*kc.y + kc.z*kc.z + kc.w*kc.w;
        }
        #pragma unroll
        for (int d = 0; d < 32; d++) {
            float4 kv = ((const float4*)(K + (size_t)d * HW))[n];
            #pragma unroll
            for (int i = 0; i < 4; i++)
                acc[i][d] += qv[i].x*kv.x + qv[i].y*kv.y
                           + qv[i].z*kv.z + qv[i].w*kv.w;
        }
    }

    #pragma unroll
    for (int i = 0; i < 4; i++) {
        float out = 0.f;
        #pragma unroll
        for (int d = 0; d < 32; d++) {
            float v = acc[i][d];
            v += __shfl_xor_sync(0xffffffffu, v, 16);
            v += __shfl_xor_sync(0xffffffffu, v, 8);
            v += __shfl_xor_sync(0xffffffffu, v, 4);
            v += __shfl_xor_sync(0xffffffffu, v, 2);
            v += __shfl_xor_sync(0xffffffffu, v, 1);
            if (lane == d) out = v;
        }
        atomicAdd(&g_attn[bh*CH*CH + (c0 + i)*CH + lane], out);
    }

    #pragma unroll
    for (int i = 0; i < 4; i++) {
        float vq = qs[i], vk = ks[i];
        vq += __shfl_xor_sync(0xffffffffu, vq, 16);
        vq += __shfl_xor_sync(0xffffffffu, vq, 8);
        vq += __shfl_xor_sync(0xffffffffu, vq, 4);
        vq += __shfl_xor_sync(0xffffffffu, vq, 2);
        vq += __shfl_xor_sync(0xffffffffu, vq, 1);
        vk += __shfl_xor_sync(0xffffffffu, vk, 16);
        vk += __shfl_xor_sync(0xffffffffu, vk, 8);
        vk += __shfl_xor_sync(0xffffffffu, vk, 4);
        vk += __shfl_xor_sync(0xffffffffu, vk, 2);
        vk += __shfl_xor_sync(0xffffffffu, vk, 1);
        if (lane == 0) {
            int row = b*CDIM + hh*CH + c0 + i;
            atomicAdd(&g_ss[row], vq);
            atomicAdd(&g_ss[NROWS + row], vk);
        }
    }
}

/* ------------------------------------------------------------------ */
__global__ void softmax_kernel(const float* __restrict__ temp)
{
    const int bh = blockIdx.x;
    const int b  = bh / HEADS;
    const int hh = bh % HEADS;
    const int c  = threadIdx.y;
    const int d  = threadIdx.x;

    const int rowq = b*CDIM + hh*CH + c;
    const int rowk = b*CDIM + hh*CH + d;
    float rq = 1.f / fmaxf(sqrtf(g_ss[rowq]), 1e-12f);
    float rk = 1.f / fmaxf(sqrtf(g_ss[NROWS + rowk]), 1e-12f);

    int idx = bh*CH*CH + c*CH + d;
    float v = g_attn[idx] * rq * rk * temp[hh];

    float m = v;
    m = fmaxf(m, __shfl_xor_sync(0xffffffffu, m, 16));
    m = fmaxf(m, __shfl_xor_sync(0xffffffffu, m, 8));
    m = fmaxf(m, __shfl_xor_sync(0xffffffffu, m, 4));
    m = fmaxf(m, __shfl_xor_sync(0xffffffffu, m, 2));
    m = fmaxf(m, __shfl_xor_sync(0xffffffffu, m, 1));
    float e = __expf(v - m);
    float s = e;
    s += __shfl_xor_sync(0xffffffffu, s, 16);
    s += __shfl_xor_sync(0xffffffffu, s, 8);
    s += __shfl_xor_sync(0xffffffffu, s, 4);
    s += __shfl_xor_sync(0xffffffffu, s, 2);
    s += __shfl_xor_sync(0xffffffffu, s, 1);
    g_attn[idx] = e / s;
}

/* ------------------------------------------------------------------ */
__global__ void weff_kernel(const float* __restrict__ wo)
{
    const int b   = blockIdx.y;
    const int idx = blockIdx.x * 256 + threadIdx.x;
    const int o   = idx / CDIM;
    const int dg  = idx % CDIM;
    const int h   = dg / CH;
    const int dc  = dg % CH;

    const float* P    = g_attn + ((b*HEADS + h)*CH)*CH;
    const float* wrow = wo + o*CDIM + h*CH;
    float s = 0.f;
    #pragma unroll
    for (int c = 0; c < CH; c++)
        s += wrow[c] * P[c*CH + dc];

    size_t off = (size_t)b*WSZ + o*CDIM + dg;
    __nv_bfloat16 hw = __float2bfloat16(s);
    g_weffh[off] = hw;
    g_weffl[off] = __float2bfloat16(s - __bfloat162float(hw));
}

/* ------------------------------------------------------------------ */
extern "C" void kernel_launch(void* const* d_in, const int* in_sizes, int n_in,
                              void* d_out, int out_size)
{
    const float* q    = (const float*)d_in[0];
    const float* k    = (const float*)d_in[1];
    const float* v    = (const float*)d_in[2];
    const float* wq   = (const float*)d_in[3];
    const float* bq   = (const float*)d_in[4];
    const float* wk   = (const float*)d_in[5];
    const float* bk   = (const float*)d_in[6];
    const float* wv   = (const float*)d_in[7];
    const float* bv   = (const float*)d_in[8];
    const float* wo   = (const float*)d_in[9];
    const float* bo   = (const float*)d_in[10];
    const float* temp = (const float*)d_in[11];

    float *qp, *kp, *vp;
    __nv_bfloat16 *wh, *wl, *weh, *wel;
    cudaGetSymbolAddress((void**)&qp,  g_qp);
    cudaGetSymbolAddress((void**)&kp,  g_kp);
    cudaGetSymbolAddress((void**)&vp,  g_vp);
    cudaGetSymbolAddress((void**)&wh,  g_wh);
    cudaGetSymbolAddress((void**)&wl,  g_wl);
    cudaGetSymbolAddress((void**)&weh, g_weffh);
    cudaGetSymbolAddress((void**)&wel, g_weffl);

    const int smem_bytes = S_WORDS * 4;
    cudaFuncSetAttribute(gemm_bf16, cudaFuncAttributeMaxDynamicSharedMemorySize,
                         smem_bytes);

    zero_kernel<<<(NBH*CH*CH + 255)/256, 256>>>();
    prep_w<<<(3*WSZ + 255)/256, 256>>>(wq, wk, wv);

    dim3 gg(HW/128, BATCH);
    gemm_bf16<<<gg, 512, smem_bytes>>>(q, wh + 0*WSZ, wl + 0*WSZ, bq, qp, 0);
    gemm_bf16<<<gg, 512, smem_bytes>>>(k, wh + 1*WSZ, wl + 1*WSZ, bk, kp, 0);
    gemm_bf16<<<gg, 512, smem_bytes>>>(v, wh + 2*WSZ, wl + 2*WSZ, bv, vp, 0);

    attn_kernel<<<dim3(NBH, ATT_CHUNKS), 256>>>(qp, kp);
    softmax_kernel<<<NBH, dim3(32, 32)>>>(temp);
    weff_kernel<<<dim3((CDIM*CDIM)/256, BATCH), 256>>>(wo);

    gemm_bf16<<<gg, 512, smem_bytes>>>(vp, weh, wel, bo, (float*)d_out, WSZ);
}